// round 1
// baseline (speedup 1.0000x reference)
#include <cuda_runtime.h>

#define ND 32768
#define NE 524288
#define DD 128
#define NH 8

// ---------------- scratch (static device memory; no allocations) ----------------
__device__ float    g_Qnodes[(size_t)ND * DD];   // 16 MB
__device__ float    g_V[(size_t)NE * DD];        // 256 MB
__device__ float    g_logits[(size_t)NE * NH];   // 16 MB
__device__ unsigned g_segmax[ND * NH];           // 1 MB
__device__ float    g_segsum[ND * NH];           // 1 MB
__device__ float    g_agg[ND * DD];              // 16 MB
__device__ float    g_bqeff[DD];

// ---------------- init ----------------
__global__ void k_init() {
    int stride = gridDim.x * blockDim.x;
    int t0 = blockIdx.x * blockDim.x + threadIdx.x;
    for (int i = t0; i < ND * DD; i += stride) g_agg[i] = 0.f;
    for (int i = t0; i < ND * NH; i += stride) { g_segsum[i] = 0.f; g_segmax[i] = 0u; }
}

// bq_eff[j] = bq[j] + sum_t cos(tb[t]) * Wq[j, 128+t]   (zero_time_feat folded into bias)
__global__ void k_bqeff(const float* __restrict__ Wq, const float* __restrict__ bq,
                        const float* __restrict__ tb) {
    int j = threadIdx.x;
    float s = bq[j];
    for (int t = 0; t < DD; t++) s += cosf(tb[t]) * Wq[j * 256 + 128 + t];
    g_bqeff[j] = s;
}

// ---------------- GEMM tiling constants ----------------
// BM=128 rows, BN=128 cols (full output width), BK=32, 256 threads, 8x8 microtile.

// ---------------- Q projection: Q_nodes = h_dst @ Wq[:, :128]^T + bq_eff ----------------
__global__ void __launch_bounds__(256) k_gemmQ(const float* __restrict__ h,
                                               const float* __restrict__ Wq) {
    __shared__ float As[32][132];
    __shared__ float Bs[32][132];
    int tid = threadIdx.x, tx = tid & 15, ty = tid >> 4;
    int m0 = blockIdx.x * 128;
    float c[8][8];
#pragma unroll
    for (int i = 0; i < 8; i++)
#pragma unroll
        for (int j = 0; j < 8; j++) c[i][j] = 0.f;

    for (int kc = 0; kc < 128; kc += 32) {
#pragma unroll
        for (int r = 0; r < 16; r++) {
            int t = tid + r * 256;
            int m = t >> 5, k = t & 31;
            As[k][m] = h[(size_t)(m0 + m) * DD + kc + k];
            Bs[k][m] = Wq[m * 256 + kc + k];
        }
        __syncthreads();
#pragma unroll 8
        for (int k = 0; k < 32; k++) {
            float a[8], b[8];
            *(float4*)&a[0] = *(const float4*)&As[k][ty * 8];
            *(float4*)&a[4] = *(const float4*)&As[k][ty * 8 + 4];
            *(float4*)&b[0] = *(const float4*)&Bs[k][tx * 8];
            *(float4*)&b[4] = *(const float4*)&Bs[k][tx * 8 + 4];
#pragma unroll
            for (int i = 0; i < 8; i++)
#pragma unroll
                for (int j = 0; j < 8; j++) c[i][j] = fmaf(a[i], b[j], c[i][j]);
        }
        __syncthreads();
    }

#pragma unroll
    for (int i = 0; i < 8; i++) {
        int m = m0 + ty * 8 + i;
#pragma unroll
        for (int jg = 0; jg < 2; jg++) {
            float4 o;
            o.x = c[i][jg * 4 + 0] + g_bqeff[tx * 8 + jg * 4 + 0];
            o.y = c[i][jg * 4 + 1] + g_bqeff[tx * 8 + jg * 4 + 1];
            o.z = c[i][jg * 4 + 2] + g_bqeff[tx * 8 + jg * 4 + 2];
            o.w = c[i][jg * 4 + 3] + g_bqeff[tx * 8 + jg * 4 + 3];
            *(float4*)&g_Qnodes[(size_t)m * DD + tx * 8 + jg * 4] = o;
        }
    }
}

// KV_in element generator: [h_src | f | cos(dt*freq + tb)]
__device__ __forceinline__ float kv_in_elem(const float* __restrict__ h,
                                            const float* __restrict__ f,
                                            const float* __restrict__ dt,
                                            const float* __restrict__ freq,
                                            const float* __restrict__ tb,
                                            int e, int kg) {
    if (kg < 128) return h[(size_t)(ND + e) * DD + kg];
    if (kg < 256) return f[(size_t)e * DD + (kg - 128)];
    return cosf(fmaf(dt[e], freq[kg - 256], tb[kg - 256]));
}

// ---------------- K projection fused with logits + segment-max ----------------
__global__ void __launch_bounds__(256) k_gemmK(const float* __restrict__ h,
                                               const float* __restrict__ f,
                                               const float* __restrict__ dt,
                                               const float* __restrict__ freq,
                                               const float* __restrict__ tb,
                                               const float* __restrict__ Wk,
                                               const float* __restrict__ bk,
                                               const int* __restrict__ dst_idx) {
    __shared__ float As[32][132];
    __shared__ float Bs[32][132];
    int tid = threadIdx.x, tx = tid & 15, ty = tid >> 4;
    int e0 = blockIdx.x * 128;
    float c[8][8];
#pragma unroll
    for (int i = 0; i < 8; i++)
#pragma unroll
        for (int j = 0; j < 8; j++) c[i][j] = 0.f;

    for (int kc = 0; kc < 384; kc += 32) {
#pragma unroll
        for (int r = 0; r < 16; r++) {
            int t = tid + r * 256;
            int m = t >> 5, k = t & 31;
            As[k][m] = kv_in_elem(h, f, dt, freq, tb, e0 + m, kc + k);
            Bs[k][m] = Wk[m * 384 + kc + k];
        }
        __syncthreads();
#pragma unroll 8
        for (int k = 0; k < 32; k++) {
            float a[8], b[8];
            *(float4*)&a[0] = *(const float4*)&As[k][ty * 8];
            *(float4*)&a[4] = *(const float4*)&As[k][ty * 8 + 4];
            *(float4*)&b[0] = *(const float4*)&Bs[k][tx * 8];
            *(float4*)&b[4] = *(const float4*)&Bs[k][tx * 8 + 4];
#pragma unroll
            for (int i = 0; i < 8; i++)
#pragma unroll
                for (int j = 0; j < 8; j++) c[i][j] = fmaf(a[i], b[j], c[i][j]);
        }
        __syncthreads();
    }

    // Epilogue: logits[e,head] = leaky_relu( sum_{col in head} K[e,col] * Q[dst,col] )
    float bkv[8];
#pragma unroll
    for (int j = 0; j < 8; j++) bkv[j] = bk[tx * 8 + j];
    int head = tx >> 1;
#pragma unroll
    for (int i = 0; i < 8; i++) {
        int e = e0 + ty * 8 + i;
        int dsti = dst_idx[e];
        const float* qr = &g_Qnodes[(size_t)dsti * DD + tx * 8];
        float4 q0 = *(const float4*)qr;
        float4 q1 = *(const float4*)(qr + 4);
        float p = (c[i][0] + bkv[0]) * q0.x + (c[i][1] + bkv[1]) * q0.y +
                  (c[i][2] + bkv[2]) * q0.z + (c[i][3] + bkv[3]) * q0.w +
                  (c[i][4] + bkv[4]) * q1.x + (c[i][5] + bkv[5]) * q1.y +
                  (c[i][6] + bkv[6]) * q1.z + (c[i][7] + bkv[7]) * q1.w;
        p += __shfl_down_sync(0xffffffffu, p, 1);
        if (!(tx & 1)) {
            float l = p > 0.f ? p : 0.2f * p;
            g_logits[(size_t)e * NH + head] = l;
            unsigned key = __float_as_uint(l);
            key = (l >= 0.f) ? (key | 0x80000000u) : ~key;
            atomicMax(&g_segmax[dsti * NH + head], key);
        }
    }
}

// ---------------- V projection ----------------
__global__ void __launch_bounds__(256) k_gemmV(const float* __restrict__ h,
                                               const float* __restrict__ f,
                                               const float* __restrict__ dt,
                                               const float* __restrict__ freq,
                                               const float* __restrict__ tb,
                                               const float* __restrict__ Wv,
                                               const float* __restrict__ bv) {
    __shared__ float As[32][132];
    __shared__ float Bs[32][132];
    int tid = threadIdx.x, tx = tid & 15, ty = tid >> 4;
    int e0 = blockIdx.x * 128;
    float c[8][8];
#pragma unroll
    for (int i = 0; i < 8; i++)
#pragma unroll
        for (int j = 0; j < 8; j++) c[i][j] = 0.f;

    for (int kc = 0; kc < 384; kc += 32) {
#pragma unroll
        for (int r = 0; r < 16; r++) {
            int t = tid + r * 256;
            int m = t >> 5, k = t & 31;
            As[k][m] = kv_in_elem(h, f, dt, freq, tb, e0 + m, kc + k);
            Bs[k][m] = Wv[m * 384 + kc + k];
        }
        __syncthreads();
#pragma unroll 8
        for (int k = 0; k < 32; k++) {
            float a[8], b[8];
            *(float4*)&a[0] = *(const float4*)&As[k][ty * 8];
            *(float4*)&a[4] = *(const float4*)&As[k][ty * 8 + 4];
            *(float4*)&b[0] = *(const float4*)&Bs[k][tx * 8];
            *(float4*)&b[4] = *(const float4*)&Bs[k][tx * 8 + 4];
#pragma unroll
            for (int i = 0; i < 8; i++)
#pragma unroll
                for (int j = 0; j < 8; j++) c[i][j] = fmaf(a[i], b[j], c[i][j]);
        }
        __syncthreads();
    }

    float bvv[8];
#pragma unroll
    for (int j = 0; j < 8; j++) bvv[j] = bv[tx * 8 + j];
#pragma unroll
    for (int i = 0; i < 8; i++) {
        int e = e0 + ty * 8 + i;
#pragma unroll
        for (int jg = 0; jg < 2; jg++) {
            float4 o;
            o.x = c[i][jg * 4 + 0] + bvv[jg * 4 + 0];
            o.y = c[i][jg * 4 + 1] + bvv[jg * 4 + 1];
            o.z = c[i][jg * 4 + 2] + bvv[jg * 4 + 2];
            o.w = c[i][jg * 4 + 3] + bvv[jg * 4 + 3];
            *(float4*)&g_V[(size_t)e * DD + tx * 8 + jg * 4] = o;
        }
    }
}

// ---------------- segment softmax: ex + segment sums ----------------
__global__ void k_softmax(const int* __restrict__ dst_idx) {
    int i = blockIdx.x * blockDim.x + threadIdx.x;
    if (i >= NE * NH) return;
    int e = i >> 3, hh = i & 7;
    int dsti = dst_idx[e];
    unsigned key = g_segmax[dsti * NH + hh];
    float m = (key & 0x80000000u) ? __uint_as_float(key & 0x7FFFFFFFu) : __uint_as_float(~key);
    float ex = expf(g_logits[i] - m);
    g_logits[i] = ex;
    atomicAdd(&g_segsum[dsti * NH + hh], ex);
}

// ---------------- weighted aggregation: agg[dst] += att * V[e] ----------------
__global__ void k_agg(const int* __restrict__ dst_idx) {
    int i = blockIdx.x * blockDim.x + threadIdx.x;
    if (i >= NE * 32) return;
    int e = i >> 5, g = i & 31, hh = g >> 2;
    int dsti = dst_idx[e];
    float att = g_logits[(size_t)e * NH + hh] / g_segsum[dsti * NH + hh];
    float4 v = *(const float4*)&g_V[(size_t)e * DD + g * 4];
    float* p = &g_agg[dsti * DD + g * 4];
    atomicAdd(p + 0, att * v.x);
    atomicAdd(p + 1, att * v.y);
    atomicAdd(p + 2, att * v.z);
    atomicAdd(p + 3, att * v.w);
}

// ---------------- output projection + relu + layernorm ----------------
__global__ void __launch_bounds__(256) k_gemmOut(const float* __restrict__ h,
                                                 const float* __restrict__ Wout,
                                                 const float* __restrict__ bout,
                                                 const float* __restrict__ gam,
                                                 const float* __restrict__ bet,
                                                 float* __restrict__ out) {
    __shared__ float As[32][132];
    __shared__ float Bs[32][132];
    int tid = threadIdx.x, tx = tid & 15, ty = tid >> 4;
    int m0 = blockIdx.x * 128;
    float c[8][8];
#pragma unroll
    for (int i = 0; i < 8; i++)
#pragma unroll
        for (int j = 0; j < 8; j++) c[i][j] = 0.f;

    for (int kc = 0; kc < 256; kc += 32) {
#pragma unroll
        for (int r = 0; r < 16; r++) {
            int t = tid + r * 256;
            int m = t >> 5, k = t & 31;
            int kg = kc + k;
            float v;
            if (kg < 128) v = g_agg[(m0 + m) * DD + kg];
            else v = h[(size_t)(m0 + m) * DD + (kg - 128)];
            As[k][m] = v;
            Bs[k][m] = Wout[m * 256 + kg];
        }
        __syncthreads();
#pragma unroll 8
        for (int k = 0; k < 32; k++) {
            float a[8], b[8];
            *(float4*)&a[0] = *(const float4*)&As[k][ty * 8];
            *(float4*)&a[4] = *(const float4*)&As[k][ty * 8 + 4];
            *(float4*)&b[0] = *(const float4*)&Bs[k][tx * 8];
            *(float4*)&b[4] = *(const float4*)&Bs[k][tx * 8 + 4];
#pragma unroll
            for (int i = 0; i < 8; i++)
#pragma unroll
                for (int j = 0; j < 8; j++) c[i][j] = fmaf(a[i], b[j], c[i][j]);
        }
        __syncthreads();
    }

    float bj[8], gj[8], bb[8];
#pragma unroll
    for (int j = 0; j < 8; j++) {
        int col = tx * 8 + j;
        bj[j] = bout[col];
        gj[j] = gam[col];
        bb[j] = bet[col];
    }
#pragma unroll
    for (int i = 0; i < 8; i++) {
        float x[8];
        float s = 0.f, s2 = 0.f;
#pragma unroll
        for (int j = 0; j < 8; j++) {
            x[j] = fmaxf(c[i][j] + bj[j], 0.f);
            s += x[j];
            s2 += x[j] * x[j];
        }
        // reduce across the 16 tx threads (width-16 segment of the warp)
#pragma unroll
        for (int off = 8; off >= 1; off >>= 1) {
            s  += __shfl_xor_sync(0xffffffffu, s,  off, 16);
            s2 += __shfl_xor_sync(0xffffffffu, s2, off, 16);
        }
        float mu = s * (1.f / 128.f);
        float var = s2 * (1.f / 128.f) - mu * mu;
        float inv = rsqrtf(fmaxf(var, 0.f) + 1e-5f);
        int m = m0 + ty * 8 + i;
#pragma unroll
        for (int jg = 0; jg < 2; jg++) {
            float4 o;
            o.x = (x[jg * 4 + 0] - mu) * inv * gj[jg * 4 + 0] + bb[jg * 4 + 0];
            o.y = (x[jg * 4 + 1] - mu) * inv * gj[jg * 4 + 1] + bb[jg * 4 + 1];
            o.z = (x[jg * 4 + 2] - mu) * inv * gj[jg * 4 + 2] + bb[jg * 4 + 2];
            o.w = (x[jg * 4 + 3] - mu) * inv * gj[jg * 4 + 3] + bb[jg * 4 + 3];
            *(float4*)&out[(size_t)m * DD + tx * 8 + jg * 4] = o;
        }
    }
}

// ---------------- launch ----------------
extern "C" void kernel_launch(void* const* d_in, const int* in_sizes, int n_in,
                              void* d_out, int out_size) {
    const float* h    = (const float*)d_in[0];
    const float* f    = (const float*)d_in[1];
    const float* dt   = (const float*)d_in[2];
    const int*   dst  = (const int*)d_in[3];
    const float* freq = (const float*)d_in[4];
    const float* tb   = (const float*)d_in[5];
    const float* Wq   = (const float*)d_in[6];
    const float* bq   = (const float*)d_in[7];
    const float* Wk   = (const float*)d_in[8];
    const float* bk   = (const float*)d_in[9];
    const float* Wv   = (const float*)d_in[10];
    const float* bv   = (const float*)d_in[11];
    const float* Wout = (const float*)d_in[12];
    const float* bout = (const float*)d_in[13];
    const float* gam  = (const float*)d_in[14];
    const float* bet  = (const float*)d_in[15];
    float* out = (float*)d_out;

    k_init<<<2048, 256>>>();
    k_bqeff<<<1, 128>>>(Wq, bq, tb);
    k_gemmQ<<<ND / 128, 256>>>(h, Wq);
    k_gemmK<<<NE / 128, 256>>>(h, f, dt, freq, tb, Wk, bk, dst);
    k_gemmV<<<NE / 128, 256>>>(h, f, dt, freq, tb, Wv, bv);
    k_softmax<<<(NE * NH) / 256, 256>>>(dst);
    k_agg<<<(NE * 32) / 256, 256>>>(dst);
    k_gemmOut<<<ND / 128, 256>>>(h, Wout, bout, gam, bet, out);
}

// round 3
// speedup vs baseline: 2.8114x; 2.8114x over previous
#include <cuda_runtime.h>
#include <cuda_bf16.h>
#include <cstdint>

#define ND 32768
#define NE 524288
#define DD 128
#define NH 8

// Does this device pass support arch-specific tcgen05 (sm_100a/sm_103a)?
#if defined(__CUDA_ARCH_FEAT_SM103_ALL) || defined(__CUDA_ARCH_FEAT_SM100_ALL) || defined(__CUDA_ARCH_FEAT_SM101_ALL)
#define TC_PATH 1
#else
#define TC_PATH 0
#endif

// ---------------- scratch (static device memory; no allocations) ----------------
__device__ float    g_Qnodes[(size_t)ND * DD];   // 16 MB
__device__ float    g_V[(size_t)NE * DD];        // 256 MB
__device__ float    g_logits[(size_t)NE * NH];   // 16 MB
__device__ unsigned g_segmax[ND * NH];           // 1 MB
__device__ float    g_segsum[ND * NH];           // 1 MB
__device__ float    g_agg[ND * DD];              // 16 MB
__device__ float    g_bqeff[DD];

// ================= PTX helpers =================
__device__ __forceinline__ uint32_t smem_u32(const void* p) {
    uint32_t a;
    asm("{ .reg .u64 t; cvta.to.shared.u64 t, %1; cvt.u32.u64 %0, t; }" : "=r"(a) : "l"(p));
    return a;
}
__device__ __forceinline__ uint32_t elect_one() {
    uint32_t pred;
    asm volatile("{\n\t.reg .pred p;\n\telect.sync _|p, 0xFFFFFFFF;\n\tselp.b32 %0, 1, 0, p;\n\t}" : "=r"(pred));
    return pred;
}
#define MBAR_INIT(a, c) asm volatile("mbarrier.init.shared.b64 [%0], %1;" :: "r"(a), "r"(c) : "memory")
#define MBAR_WAIT(a, ph) do { \
    uint32_t _m = (a); uint32_t _p = (ph); uint32_t _d; \
    asm volatile("{\n\t.reg .pred p;\n\tmbarrier.try_wait.parity.acquire.cta.shared::cta.b64 p, [%1], %2;\n\tselp.b32 %0, 1, 0, p;\n\t}" \
        : "=r"(_d) : "r"(_m), "r"(_p) : "memory"); \
    if (!_d) { \
        asm volatile("{\n\t.reg .pred P1;\n\tWL_%=:\n\tmbarrier.try_wait.parity.acquire.cta.shared::cta.b64 P1, [%0], %1, 0x989680;\n\t@P1 bra.uni WD_%=;\n\tbra.uni WL_%=;\n\tWD_%=:\n\t}" \
            :: "r"(_m), "r"(_p) : "memory"); \
    } } while (0)

#define SWZ128(o)  ((o) ^ (((o) >> 3) & 0x70))

// ---------------- SMEM layout for k_kv (dynamic, 198656 B) ----------------
#define SM_TMEMPTR 0
#define SM_MB0     16
#define SM_MB1     24
#define SM_BK      64
#define SM_BV      576
#define SM_AHI(s)  (2048 + (s) * 16384)
#define SM_ALO(s)  (34816 + (s) * 16384)
#define SM_BHI(s)  (67584 + (s) * 32768)
#define SM_BLO(s)  (133120 + (s) * 32768)
#define SM_TOTAL   198656

// fallback layout (inside same dynamic smem)
#define FB_BK   0
#define FB_BV   512
#define FB_AHI  1024
#define FB_ALO  (1024 + 9216)
#define FB_BHI  (1024 + 18432)
#define FB_BLO  (1024 + 36864)
// total 56320 < SM_TOTAL

// ---------------- init ----------------
__global__ void k_init() {
    int stride = gridDim.x * blockDim.x;
    int t0 = blockIdx.x * blockDim.x + threadIdx.x;
    for (int i = t0; i < ND * DD; i += stride) g_agg[i] = 0.f;
    for (int i = t0; i < ND * NH; i += stride) { g_segsum[i] = 0.f; g_segmax[i] = 0u; }
}

__global__ void k_bqeff(const float* __restrict__ Wq, const float* __restrict__ bq,
                        const float* __restrict__ tb) {
    int j = threadIdx.x;
    float s = bq[j];
    for (int t = 0; t < DD; t++) s += cosf(tb[t]) * Wq[j * 256 + 128 + t];
    g_bqeff[j] = s;
}

// ---------------- Q projection (SIMT fp32, small) ----------------
__global__ void __launch_bounds__(256) k_gemmQ(const float* __restrict__ h,
                                               const float* __restrict__ Wq) {
    __shared__ float As[32][132];
    __shared__ float Bs[32][132];
    int tid = threadIdx.x, tx = tid & 15, ty = tid >> 4;
    int m0 = blockIdx.x * 128;
    float c[8][8];
#pragma unroll
    for (int i = 0; i < 8; i++)
#pragma unroll
        for (int j = 0; j < 8; j++) c[i][j] = 0.f;

    for (int kc = 0; kc < 128; kc += 32) {
#pragma unroll
        for (int r = 0; r < 16; r++) {
            int t = tid + r * 256;
            int m = t >> 5, k = t & 31;
            As[k][m] = h[(size_t)(m0 + m) * DD + kc + k];
            Bs[k][m] = Wq[m * 256 + kc + k];
        }
        __syncthreads();
#pragma unroll 8
        for (int k = 0; k < 32; k++) {
            float a[8], b[8];
            *(float4*)&a[0] = *(const float4*)&As[k][ty * 8];
            *(float4*)&a[4] = *(const float4*)&As[k][ty * 8 + 4];
            *(float4*)&b[0] = *(const float4*)&Bs[k][tx * 8];
            *(float4*)&b[4] = *(const float4*)&Bs[k][tx * 8 + 4];
#pragma unroll
            for (int i = 0; i < 8; i++)
#pragma unroll
                for (int j = 0; j < 8; j++) c[i][j] = fmaf(a[i], b[j], c[i][j]);
        }
        __syncthreads();
    }
#pragma unroll
    for (int i = 0; i < 8; i++) {
        int m = m0 + ty * 8 + i;
#pragma unroll
        for (int jg = 0; jg < 2; jg++) {
            float4 o;
            o.x = c[i][jg * 4 + 0] + g_bqeff[tx * 8 + jg * 4 + 0];
            o.y = c[i][jg * 4 + 1] + g_bqeff[tx * 8 + jg * 4 + 1];
            o.z = c[i][jg * 4 + 2] + g_bqeff[tx * 8 + jg * 4 + 2];
            o.w = c[i][jg * 4 + 3] + g_bqeff[tx * 8 + jg * 4 + 3];
            *(float4*)&g_Qnodes[(size_t)m * DD + tx * 8 + jg * 4] = o;
        }
    }
}

// KV_in quad generator (4 consecutive k of row e, chunk c covers k [c*32, c*32+32))
__device__ __forceinline__ float4 kv_quad(const float* __restrict__ h,
                                          const float* __restrict__ f,
                                          const float* __restrict__ dt,
                                          const float* __restrict__ freq,
                                          const float* __restrict__ tb,
                                          int e, int c, int kq) {
    float4 v;
    if (c < 4) {
        v = *(const float4*)&h[(size_t)(ND + e) * DD + c * 32 + kq];
    } else if (c < 8) {
        v = *(const float4*)&f[(size_t)e * DD + (c - 4) * 32 + kq];
    } else {
        int ko = (c - 8) * 32 + kq;
        float d = dt[e];
        float4 fr = *(const float4*)&freq[ko];
        float4 tv = *(const float4*)&tb[ko];
        v.x = cosf(fmaf(d, fr.x, tv.x));
        v.y = cosf(fmaf(d, fr.y, tv.y));
        v.z = cosf(fmaf(d, fr.z, tv.z));
        v.w = cosf(fmaf(d, fr.w, tv.w));
    }
    return v;
}

#if TC_PATH
// ======== tcgen05 TF32 (3x compensated) machinery ========
#define TC_ALLOC(sa, n)   asm volatile("tcgen05.alloc.cta_group::1.sync.aligned.shared::cta.b32 [%0], %1;" :: "r"(sa), "r"(n) : "memory")
#define TC_DEALLOC(t, n)  asm volatile("tcgen05.dealloc.cta_group::1.sync.aligned.b32 %0, %1;" :: "r"(t), "r"(n))
#define TC_RELINQ()       asm volatile("tcgen05.relinquish_alloc_permit.cta_group::1.sync.aligned;")
#define TC_COMMIT(mb)     asm volatile("tcgen05.commit.cta_group::1.mbarrier::arrive::one.shared::cluster.b64 [%0];" :: "r"(mb) : "memory")
#define TC_WAIT_LD()      asm volatile("tcgen05.wait::ld.sync.aligned;" ::: "memory")
#define TC_FENCE_AFTER()  asm volatile("tcgen05.fence::after_thread_sync;" ::: "memory")
#define FENCE_ASYNC()     asm volatile("fence.proxy.async.shared::cta;" ::: "memory")

#define TC_LD_X32(r, ta) \
    asm volatile("tcgen05.ld.sync.aligned.32x32b.x32.b32 " \
        "{%0,%1,%2,%3,%4,%5,%6,%7,%8,%9,%10,%11,%12,%13,%14,%15," \
        "%16,%17,%18,%19,%20,%21,%22,%23,%24,%25,%26,%27,%28,%29,%30,%31}, [%32];" \
        : "=r"((r)[0]),"=r"((r)[1]),"=r"((r)[2]),"=r"((r)[3]),"=r"((r)[4]),"=r"((r)[5]),"=r"((r)[6]),"=r"((r)[7]), \
          "=r"((r)[8]),"=r"((r)[9]),"=r"((r)[10]),"=r"((r)[11]),"=r"((r)[12]),"=r"((r)[13]),"=r"((r)[14]),"=r"((r)[15]), \
          "=r"((r)[16]),"=r"((r)[17]),"=r"((r)[18]),"=r"((r)[19]),"=r"((r)[20]),"=r"((r)[21]),"=r"((r)[22]),"=r"((r)[23]), \
          "=r"((r)[24]),"=r"((r)[25]),"=r"((r)[26]),"=r"((r)[27]),"=r"((r)[28]),"=r"((r)[29]),"=r"((r)[30]),"=r"((r)[31]) \
        : "r"(ta))

static constexpr uint64_t SMEM_DESC_BASE_SW128 =
    (uint64_t(2) << 61) | (uint64_t(1) << 46) | (uint64_t(64) << 32) | (uint64_t(1) << 16);
#define MK_DESC(a) (SMEM_DESC_BASE_SW128 | ((uint64_t)((a) >> 4) & 0x3FFF))

// idesc: dtype=F32(1<<4), atype=TF32(2<<7), btype=TF32(2<<10), N=128(16<<17), M=128(8<<24)
static constexpr uint32_t IDESC_TF32 =
    (1u << 4) | (2u << 7) | (2u << 10) | (16u << 17) | (8u << 24);

__device__ __forceinline__ void mma_tf32(uint32_t d, uint64_t ad, uint64_t bd, uint32_t en) {
    asm volatile(
        "{\n\t.reg .pred p;\n\tsetp.ne.u32 p, %4, 0;\n\t"
        "tcgen05.mma.cta_group::1.kind::tf32 [%0], %1, %2, %3, {%5, %5, %5, %5}, p;\n\t}"
        :: "r"(d), "l"(ad), "l"(bd), "r"(IDESC_TF32), "r"(en), "r"(0u) : "memory");
}

__device__ __forceinline__ uint32_t f2tf(float v) {
    uint32_t r;
    asm("cvt.rna.tf32.f32 %0, %1;" : "=r"(r) : "f"(v));
    return r;
}

__device__ __forceinline__ void sts_hilo(uint32_t baseHi, uint32_t baseLo, uint32_t off, float4 v) {
    uint32_t sw = SWZ128(off);
    uint32_t h0 = f2tf(v.x), h1 = f2tf(v.y), h2 = f2tf(v.z), h3 = f2tf(v.w);
    uint32_t l0 = f2tf(v.x - __uint_as_float(h0));
    uint32_t l1 = f2tf(v.y - __uint_as_float(h1));
    uint32_t l2 = f2tf(v.z - __uint_as_float(h2));
    uint32_t l3 = f2tf(v.w - __uint_as_float(h3));
    asm volatile("st.shared.v4.b32 [%0], {%1,%2,%3,%4};" :: "r"(baseHi + sw), "r"(h0), "r"(h1), "r"(h2), "r"(h3) : "memory");
    asm volatile("st.shared.v4.b32 [%0], {%1,%2,%3,%4};" :: "r"(baseLo + sw), "r"(l0), "r"(l1), "r"(l2), "r"(l3) : "memory");
}
#else
// ======== mma.sync bf16 (hi/lo split, 3 products) machinery ========
__device__ __forceinline__ void mma_bf16(float* d, const uint32_t* a, const uint32_t* b) {
    asm volatile(
        "mma.sync.aligned.m16n8k16.row.col.f32.bf16.bf16.f32 "
        "{%0,%1,%2,%3},{%4,%5,%6,%7},{%8,%9},{%0,%1,%2,%3};"
        : "+f"(d[0]), "+f"(d[1]), "+f"(d[2]), "+f"(d[3])
        : "r"(a[0]), "r"(a[1]), "r"(a[2]), "r"(a[3]), "r"(b[0]), "r"(b[1]));
}
__device__ __forceinline__ void split2(float x, float y, uint32_t& hi, uint32_t& lo) {
    __nv_bfloat16 hx = __float2bfloat16(x), hy = __float2bfloat16(y);
    __nv_bfloat16 lx = __float2bfloat16(x - __bfloat162float(hx));
    __nv_bfloat16 ly = __float2bfloat16(y - __bfloat162float(hy));
    hi = (uint32_t)__bfloat16_as_ushort(hx) | ((uint32_t)__bfloat16_as_ushort(hy) << 16);
    lo = (uint32_t)__bfloat16_as_ushort(lx) | ((uint32_t)__bfloat16_as_ushort(ly) << 16);
}
__device__ __forceinline__ void fb_store4(uint32_t* hiA, uint32_t* loA, int halfIdx, float4 v) {
    uint32_t h0, l0, h1, l1;
    split2(v.x, v.y, h0, l0);
    split2(v.z, v.w, h1, l1);
    int i = halfIdx >> 1;
    hiA[i] = h0; hiA[i + 1] = h1;
    loA[i] = l0; loA[i + 1] = l1;
}
#endif

// ================= fused K+V projection =================
// Per CTA: 128 edges, outputs N=256 ([K | V]), reduction K-dim = 384 in 12 chunks of 32.
__global__ void __launch_bounds__(512, 1) k_kv(const float* __restrict__ h,
                                               const float* __restrict__ f,
                                               const float* __restrict__ dt,
                                               const float* __restrict__ freq,
                                               const float* __restrict__ tb,
                                               const float* __restrict__ Wk,
                                               const float* __restrict__ bk,
                                               const float* __restrict__ Wv,
                                               const float* __restrict__ bv,
                                               const int* __restrict__ dst_idx) {
    extern __shared__ char smem[];
    int tid = threadIdx.x, wid = tid >> 5, lane = tid & 31;
    int e0 = blockIdx.x * 128;

#if TC_PATH
    // ---------------- tcgen05 TF32 path ----------------
    uint32_t sb = smem_u32(smem);
    if (wid == 0) {
        TC_ALLOC(sb + SM_TMEMPTR, 256);
        TC_RELINQ();
    }
    if (tid == 0) { MBAR_INIT(sb + SM_MB0, 1); MBAR_INIT(sb + SM_MB1, 1); }
    if (tid < 128) {
        ((float*)(smem + SM_BK))[tid] = bk[tid];
        ((float*)(smem + SM_BV))[tid] = bv[tid];
    }
    __syncthreads();
    uint32_t tmem;
    asm volatile("ld.shared.b32 %0, [%1];" : "=r"(tmem) : "r"(sb + SM_TMEMPTR));

    int ph0 = 0, ph1 = 0;
    for (int c = 0; c < 12; c++) {
        int s = c & 1;
        if (c >= 2) {
            if (s == 0) { MBAR_WAIT(sb + SM_MB0, ph0); ph0 ^= 1; }
            else        { MBAR_WAIT(sb + SM_MB1, ph1); ph1 ^= 1; }
        }
        uint32_t aHi = sb + SM_AHI(s), aLo = sb + SM_ALO(s);
        uint32_t bHi = sb + SM_BHI(s), bLo = sb + SM_BLO(s);

        // A: 128 x 32 f32 (1024 quads)
#pragma unroll
        for (int r = 0; r < 2; r++) {
            int idx = tid + r * 512;
            int m = idx >> 3, kq = (idx & 7) * 4;
            float4 v = kv_quad(h, f, dt, freq, tb, e0 + m, c, kq);
            sts_hilo(aHi, aLo, (uint32_t)(m * 128 + kq * 4), v);
        }
        // B: 256 x 32 f32 (2048 quads)
#pragma unroll
        for (int r = 0; r < 4; r++) {
            int idx = tid + r * 512;
            int n = idx >> 3, kq = (idx & 7) * 4;
            const float* src = (n < 128) ? &Wk[n * 384 + c * 32 + kq]
                                         : &Wv[(n - 128) * 384 + c * 32 + kq];
            float4 v = *(const float4*)src;
            sts_hilo(bHi, bLo, (uint32_t)(n * 128 + kq * 4), v);
        }
        FENCE_ASYNC();
        __syncthreads();

        if (wid == 0 && elect_one()) {
            uint64_t dAh = MK_DESC(aHi), dAl = MK_DESC(aLo);
            uint64_t dBh0 = MK_DESC(bHi), dBh1 = MK_DESC(bHi + 16384);
            uint64_t dBl0 = MK_DESC(bLo), dBl1 = MK_DESC(bLo + 16384);
#pragma unroll
            for (int ks = 0; ks < 4; ks++) {
                uint32_t first = (c == 0 && ks == 0) ? 0u : 1u;
                mma_tf32(tmem + 0,   dAh + ks * 2, dBh0 + ks * 2, first);
                mma_tf32(tmem + 0,   dAl + ks * 2, dBh0 + ks * 2, 1u);
                mma_tf32(tmem + 0,   dAh + ks * 2, dBl0 + ks * 2, 1u);
                mma_tf32(tmem + 128, dAh + ks * 2, dBh1 + ks * 2, first);
                mma_tf32(tmem + 128, dAl + ks * 2, dBh1 + ks * 2, 1u);
                mma_tf32(tmem + 128, dAh + ks * 2, dBl1 + ks * 2, 1u);
            }
            TC_COMMIT(sb + (s ? SM_MB1 : SM_MB0));
        }
    }
    MBAR_WAIT(sb + SM_MB1, ph1);   // c=11's commit
    TC_FENCE_AFTER();

    // epilogue: warps 0-3 handle K (logits), warps 4-7 handle V; subpartition = wid&3
    if (wid < 4) {
        int e = e0 + (wid & 3) * 32 + lane;
        int dsti = dst_idx[e];
        const float* sbk = (const float*)(smem + SM_BK);
        const float* qrow = &g_Qnodes[(size_t)dsti * DD];
        float part[NH];
#pragma unroll
        for (int hh = 0; hh < NH; hh++) part[hh] = 0.f;
#pragma unroll
        for (int cb = 0; cb < 4; cb++) {
            uint32_t r[32];
            TC_LD_X32(r, tmem + cb * 32);
            TC_WAIT_LD();
#pragma unroll
            for (int j = 0; j < 32; j++) {
                int col = cb * 32 + j;
                float kv = __uint_as_float(r[j]) + sbk[col];
                part[col >> 4] = fmaf(kv, qrow[col], part[col >> 4]);
            }
        }
#pragma unroll
        for (int hh = 0; hh < NH; hh++) {
            float p = part[hh];
            float l = p > 0.f ? p : 0.2f * p;
            g_logits[(size_t)e * NH + hh] = l;
            unsigned key = __float_as_uint(l);
            key = (l >= 0.f) ? (key | 0x80000000u) : ~key;
            atomicMax(&g_segmax[dsti * NH + hh], key);
        }
    } else {
        int e = e0 + (wid & 3) * 32 + lane;
        const float* sbv = (const float*)(smem + SM_BV);
#pragma unroll
        for (int cb = 0; cb < 4; cb++) {
            uint32_t r[32];
            TC_LD_X32(r, tmem + 128 + cb * 32);
            TC_WAIT_LD();
#pragma unroll
            for (int jg = 0; jg < 8; jg++) {
                float4 o;
                o.x = __uint_as_float(r[jg * 4 + 0]) + sbv[cb * 32 + jg * 4 + 0];
                o.y = __uint_as_float(r[jg * 4 + 1]) + sbv[cb * 32 + jg * 4 + 1];
                o.z = __uint_as_float(r[jg * 4 + 2]) + sbv[cb * 32 + jg * 4 + 2];
                o.w = __uint_as_float(r[jg * 4 + 3]) + sbv[cb * 32 + jg * 4 + 3];
                *(float4*)&g_V[(size_t)e * DD + cb * 32 + jg * 4] = o;
            }
        }
    }
    __syncthreads();
    if (wid == 0) TC_DEALLOC(tmem, 256);

#else
    // ---------------- mma.sync bf16 fallback (generic target) ----------------
    float* sbk = (float*)(smem + FB_BK);
    float* sbv = (float*)(smem + FB_BV);
    uint32_t* AH = (uint32_t*)(smem + FB_AHI);
    uint32_t* AL = (uint32_t*)(smem + FB_ALO);
    uint32_t* BH = (uint32_t*)(smem + FB_BHI);
    uint32_t* BL = (uint32_t*)(smem + FB_BLO);
    if (tid < 128) { sbk[tid] = bk[tid]; sbv[tid] = bv[tid]; }

    int wm = wid & 3, wn = wid >> 2;      // 4 warps in M x 4 warps in N
    int qr = lane >> 2, qc = (lane & 3) * 2;
    float d[2][8][4];
#pragma unroll
    for (int mt = 0; mt < 2; mt++)
#pragma unroll
        for (int nt = 0; nt < 8; nt++)
#pragma unroll
            for (int j = 0; j < 4; j++) d[mt][nt][j] = 0.f;

    for (int c = 0; c < 12; c++) {
        __syncthreads();
        // stage A (128 x 32) hi/lo bf16, row stride 36 halves
#pragma unroll
        for (int r = 0; r < 2; r++) {
            int idx = tid + r * 512;
            int m = idx >> 3, kq = (idx & 7) * 4;
            float4 v = kv_quad(h, f, dt, freq, tb, e0 + m, c, kq);
            fb_store4(AH, AL, m * 36 + kq, v);
        }
        // stage B (256 x 32) hi/lo bf16
#pragma unroll
        for (int r = 0; r < 4; r++) {
            int idx = tid + r * 512;
            int n = idx >> 3, kq = (idx & 7) * 4;
            const float* src = (n < 128) ? &Wk[n * 384 + c * 32 + kq]
                                         : &Wv[(n - 128) * 384 + c * 32 + kq];
            float4 v = *(const float4*)src;
            fb_store4(BH, BL, n * 36 + kq, v);
        }
        __syncthreads();

#pragma unroll
        for (int ks = 0; ks < 2; ks++) {
            int kk = ks * 16 + qc;
            uint32_t bh[8][2], bl[8][2];
#pragma unroll
            for (int nt = 0; nt < 8; nt++) {
                int n = wn * 64 + nt * 8 + qr;
                int i0 = n * 18 + (kk >> 1);
                bh[nt][0] = BH[i0]; bh[nt][1] = BH[i0 + 4];
                bl[nt][0] = BL[i0]; bl[nt][1] = BL[i0 + 4];
            }
#pragma unroll
            for (int mt = 0; mt < 2; mt++) {
                int rrow = wm * 32 + mt * 16 + qr;
                int i0 = rrow * 18 + (kk >> 1);
                uint32_t ah[4], al[4];
                ah[0] = AH[i0]; ah[1] = AH[i0 + 144]; ah[2] = AH[i0 + 4]; ah[3] = AH[i0 + 148];
                al[0] = AL[i0]; al[1] = AL[i0 + 144]; al[2] = AL[i0 + 4]; al[3] = AL[i0 + 148];
#pragma unroll
                for (int nt = 0; nt < 8; nt++) {
                    mma_bf16(d[mt][nt], ah, bh[nt]);
                    mma_bf16(d[mt][nt], ah, bl[nt]);
                    mma_bf16(d[mt][nt], al, bh[nt]);
                }
            }
        }
    }

    // epilogue
    if (wn < 2) {
        // K cols [wn*64, wn*64+64) -> heads wn*4 .. wn*4+3
#pragma unroll
        for (int mt = 0; mt < 2; mt++) {
#pragma unroll
            for (int hh2 = 0; hh2 < 2; hh2++) {
                int e = e0 + wm * 32 + mt * 16 + qr + hh2 * 8;
                int dsti = dst_idx[e];
                const float* q = &g_Qnodes[(size_t)dsti * DD];
                float part[4] = {0.f, 0.f, 0.f, 0.f};
#pragma unroll
                for (int nt = 0; nt < 8; nt++) {
                    int cc = wn * 64 + nt * 8 + qc;
                    float v0 = d[mt][nt][hh2 * 2 + 0] + sbk[cc];
                    float v1 = d[mt][nt][hh2 * 2 + 1] + sbk[cc + 1];
                    float2 qv = *(const float2*)&q[cc];
                    part[(nt * 8 + qc) >> 4] += v0 * qv.x + v1 * qv.y;
                }
#pragma unroll
                for (int i = 0; i < 4; i++) {
                    part[i] += __shfl_xor_sync(0xffffffffu, part[i], 1);
                    part[i] += __shfl_xor_sync(0xffffffffu, part[i], 2);
                }
                if ((lane & 3) == 0) {
#pragma unroll
                    for (int hh = 0; hh < 4; hh++) {
                        int head = wn * 4 + hh;
                        float p = part[hh];
                        float l = p > 0.f ? p : 0.2f * p;
                        g_logits[(size_t)e * NH + head] = l;
                        unsigned key = __float_as_uint(l);
                        key = (l >= 0.f) ? (key | 0x80000000u) : ~key;
                        atomicMax(&g_segmax[dsti * NH + head], key);
                    }
                }
            }
        }
    } else {
        int cvb = (wn - 2) * 64;
#pragma unroll
        for (int mt = 0; mt < 2; mt++) {
#pragma unroll
            for (int hh2 = 0; hh2 < 2; hh2++) {
                int e = e0 + wm * 32 + mt * 16 + qr + hh2 * 8;
#pragma unroll
                for (int nt = 0; nt < 8; nt++) {
                    int cc = cvb + nt * 8 + qc;
                    float2 o;
                    o.x = d[mt][nt][hh2 * 2 + 0] + sbv[cc];
                    o.y = d[mt][nt][hh2 * 2 + 1] + sbv[cc + 1];
                    *(float2*)&g_V[(size_t)e * DD + cc] = o;
                }
            }
        }
    }
#endif
}

// ---------------- segment softmax ----------------
__global__ void k_softmax(const int* __restrict__ dst_idx) {
    int i = blockIdx.x * blockDim.x + threadIdx.x;
    if (i >= NE * NH) return;
    int e = i >> 3, hh = i & 7;
    int dsti = dst_idx[e];
    unsigned key = g_segmax[dsti * NH + hh];
    float m = (key & 0x80000000u) ? __uint_as_float(key & 0x7FFFFFFFu) : __uint_as_float(~key);
    float ex = expf(g_logits[i] - m);
    g_logits[i] = ex;
    atomicAdd(&g_segsum[dsti * NH + hh], ex);
}

// ---------------- weighted aggregation ----------------
__global__ void k_agg(const int* __restrict__ dst_idx) {
    int i = blockIdx.x * blockDim.x + threadIdx.x;
    if (i >= NE * 32) return;
    int e = i >> 5, g = i & 31, hh = g >> 2;
    int dsti = dst_idx[e];
    float att = g_logits[(size_t)e * NH + hh] / g_segsum[dsti * NH + hh];
    float4 v = *(const float4*)&g_V[(size_t)e * DD + g * 4];
    float* p = &g_agg[dsti * DD + g * 4];
    atomicAdd(p + 0, att * v.x);
    atomicAdd(p + 1, att * v.y);
    atomicAdd(p + 2, att * v.z);
    atomicAdd(p + 3, att * v.w);
}

// ---------------- output projection + relu + layernorm ----------------
__global__ void __launch_bounds__(256) k_gemmOut(const float* __restrict__ h,
                                                 const float* __restrict__ Wout,
                                                 const float* __restrict__ bout,
                                                 const float* __restrict__ gam,
                                                 const float* __restrict__ bet,
                                                 float* __restrict__ out) {
    __shared__ float As[32][132];
    __shared__ float Bs[32][132];
    int tid = threadIdx.x, tx = tid & 15, ty = tid >> 4;
    int m0 = blockIdx.x * 128;
    float c[8][8];
#pragma unroll
    for (int i = 0; i < 8; i++)
#pragma unroll
        for (int j = 0; j < 8; j++) c[i][j] = 0.f;

    for (int kc = 0; kc < 256; kc += 32) {
#pragma unroll
        for (int r = 0; r < 16; r++) {
            int t = tid + r * 256;
            int m = t >> 5, k = t & 31;
            int kg = kc + k;
            float v;
            if (kg < 128) v = g_agg[(m0 + m) * DD + kg];
            else v = h[(size_t)(m0 + m) * DD + (kg - 128)];
            As[k][m] = v;
            Bs[k][m] = Wout[m * 256 + kg];
        }
        __syncthreads();
#pragma unroll 8
        for (int k = 0; k < 32; k++) {
            float a[8], b[8];
            *(float4*)&a[0] = *(const float4*)&As[k][ty * 8];
            *(float4*)&a[4] = *(const float4*)&As[k][ty * 8 + 4];
            *(float4*)&b[0] = *(const float4*)&Bs[k][tx * 8];
            *(float4*)&b[4] = *(const float4*)&Bs[k][tx * 8 + 4];
#pragma unroll
            for (int i = 0; i < 8; i++)
#pragma unroll
                for (int j = 0; j < 8; j++) c[i][j] = fmaf(a[i], b[j], c[i][j]);
        }
        __syncthreads();
    }

    float bj[8], gj[8], bb[8];
#pragma unroll
    for (int j = 0; j < 8; j++) {
        int col = tx * 8 + j;
        bj[j] = bout[col];
        gj[j] = gam[col];
        bb[j] = bet[col];
    }
#pragma unroll
    for (int i = 0; i < 8; i++) {
        float x[8];
        float s = 0.f, s2 = 0.f;
#pragma unroll
        for (int j = 0; j < 8; j++) {
            x[j] = fmaxf(c[i][j] + bj[j], 0.f);
            s += x[j];
            s2 += x[j] * x[j];
        }
#pragma unroll
        for (int off = 8; off >= 1; off >>= 1) {
            s  += __shfl_xor_sync(0xffffffffu, s,  off, 16);
            s2 += __shfl_xor_sync(0xffffffffu, s2, off, 16);
        }
        float mu = s * (1.f / 128.f);
        float var = s2 * (1.f / 128.f) - mu * mu;
        float inv = rsqrtf(fmaxf(var, 0.f) + 1e-5f);
        int m = m0 + ty * 8 + i;
#pragma unroll
        for (int jg = 0; jg < 2; jg++) {
            float4 o;
            o.x = (x[jg * 4 + 0] - mu) * inv * gj[jg * 4 + 0] + bb[jg * 4 + 0];
            o.y = (x[jg * 4 + 1] - mu) * inv * gj[jg * 4 + 1] + bb[jg * 4 + 1];
            o.z = (x[jg * 4 + 2] - mu) * inv * gj[jg * 4 + 2] + bb[jg * 4 + 2];
            o.w = (x[jg * 4 + 3] - mu) * inv * gj[jg * 4 + 3] + bb[jg * 4 + 3];
            *(float4*)&out[(size_t)m * DD + tx * 8 + jg * 4] = o;
        }
    }
}

// ---------------- launch ----------------
extern "C" void kernel_launch(void* const* d_in, const int* in_sizes, int n_in,
                              void* d_out, int out_size) {
    const float* h    = (const float*)d_in[0];
    const float* f    = (const float*)d_in[1];
    const float* dt   = (const float*)d_in[2];
    const int*   dst  = (const int*)d_in[3];
    const float* freq = (const float*)d_in[4];
    const float* tb   = (const float*)d_in[5];
    const float* Wq   = (const float*)d_in[6];
    const float* bq   = (const float*)d_in[7];
    const float* Wk   = (const float*)d_in[8];
    const float* bk   = (const float*)d_in[9];
    const float* Wv   = (const float*)d_in[10];
    const float* bv   = (const float*)d_in[11];
    const float* Wout = (const float*)d_in[12];
    const float* bout = (const float*)d_in[13];
    const float* gam  = (const float*)d_in[14];
    const float* bet  = (const float*)d_in[15];
    float* out = (float*)d_out;

    cudaFuncSetAttribute(k_kv, cudaFuncAttributeMaxDynamicSharedMemorySize, SM_TOTAL);

    k_init<<<2048, 256>>>();
    k_bqeff<<<1, 128>>>(Wq, bq, tb);
    k_gemmQ<<<ND / 128, 256>>>(h, Wq);
    k_kv<<<NE / 128, 512, SM_TOTAL>>>(h, f, dt, freq, tb, Wk, bk, Wv, bv, dst);
    k_softmax<<<(NE * NH) / 256, 256>>>(dst);
    k_agg<<<(NE * 32) / 256, 256>>>(dst);
    k_gemmOut<<<ND / 128, 256>>>(h, Wout, bout, gam, bet, out);
}

// round 4
// speedup vs baseline: 2.9020x; 1.0322x over previous
#include <cuda_runtime.h>
#include <cuda_bf16.h>
#include <cstdint>

#define ND 32768
#define NE 524288
#define DD 128
#define NH 8

// ---------------- scratch (static device memory; no allocations) ----------------
__device__ float    g_Qnodes[(size_t)ND * DD];   // 16 MB
__device__ float    g_V[(size_t)NE * DD];        // 256 MB
__device__ float    g_logits[(size_t)NE * NH];   // 16 MB
__device__ unsigned g_segmax[ND * NH];           // 1 MB
__device__ float    g_segsum[ND * NH];           // 1 MB
__device__ float    g_agg[ND * DD];              // 16 MB
__device__ float    g_bqeff[DD];

// ---------------- init ----------------
__global__ void k_init() {
    int stride = gridDim.x * blockDim.x;
    int t0 = blockIdx.x * blockDim.x + threadIdx.x;
    for (int i = t0; i < ND * DD; i += stride) g_agg[i] = 0.f;
    for (int i = t0; i < ND * NH; i += stride) { g_segsum[i] = 0.f; g_segmax[i] = 0u; }
}

__global__ void k_bqeff(const float* __restrict__ Wq, const float* __restrict__ bq,
                        const float* __restrict__ tb) {
    int j = threadIdx.x;
    float s = bq[j];
    for (int t = 0; t < DD; t++) s += cosf(tb[t]) * Wq[j * 256 + 128 + t];
    g_bqeff[j] = s;
}

// ---------------- Q projection (SIMT fp32, small) ----------------
__global__ void __launch_bounds__(256) k_gemmQ(const float* __restrict__ h,
                                               const float* __restrict__ Wq) {
    __shared__ float As[32][132];
    __shared__ float Bs[32][132];
    int tid = threadIdx.x, tx = tid & 15, ty = tid >> 4;
    int m0 = blockIdx.x * 128;
    float c[8][8];
#pragma unroll
    for (int i = 0; i < 8; i++)
#pragma unroll
        for (int j = 0; j < 8; j++) c[i][j] = 0.f;

    for (int kc = 0; kc < 128; kc += 32) {
#pragma unroll
        for (int r = 0; r < 16; r++) {
            int t = tid + r * 256;
            int m = t >> 5, k = t & 31;
            As[k][m] = h[(size_t)(m0 + m) * DD + kc + k];
            Bs[k][m] = Wq[m * 256 + kc + k];
        }
        __syncthreads();
#pragma unroll 8
        for (int k = 0; k < 32; k++) {
            float a[8], b[8];
            *(float4*)&a[0] = *(const float4*)&As[k][ty * 8];
            *(float4*)&a[4] = *(const float4*)&As[k][ty * 8 + 4];
            *(float4*)&b[0] = *(const float4*)&Bs[k][tx * 8];
            *(float4*)&b[4] = *(const float4*)&Bs[k][tx * 8 + 4];
#pragma unroll
            for (int i = 0; i < 8; i++)
#pragma unroll
                for (int j = 0; j < 8; j++) c[i][j] = fmaf(a[i], b[j], c[i][j]);
        }
        __syncthreads();
    }
#pragma unroll
    for (int i = 0; i < 8; i++) {
        int m = m0 + ty * 8 + i;
#pragma unroll
        for (int jg = 0; jg < 2; jg++) {
            float4 o;
            o.x = c[i][jg * 4 + 0] + g_bqeff[tx * 8 + jg * 4 + 0];
            o.y = c[i][jg * 4 + 1] + g_bqeff[tx * 8 + jg * 4 + 1];
            o.z = c[i][jg * 4 + 2] + g_bqeff[tx * 8 + jg * 4 + 2];
            o.w = c[i][jg * 4 + 3] + g_bqeff[tx * 8 + jg * 4 + 3];
            *(float4*)&g_Qnodes[(size_t)m * DD + tx * 8 + jg * 4] = o;
        }
    }
}

// ======== mma.sync bf16 (hi/lo split, 3 products) ========
__device__ __forceinline__ void mma_bf16(float* d, const uint32_t* a, const uint32_t* b) {
    asm volatile(
        "mma.sync.aligned.m16n8k16.row.col.f32.bf16.bf16.f32 "
        "{%0,%1,%2,%3},{%4,%5,%6,%7},{%8,%9},{%0,%1,%2,%3};"
        : "+f"(d[0]), "+f"(d[1]), "+f"(d[2]), "+f"(d[3])
        : "r"(a[0]), "r"(a[1]), "r"(a[2]), "r"(a[3]), "r"(b[0]), "r"(b[1]));
}
__device__ __forceinline__ void split2(float x, float y, uint32_t& hi, uint32_t& lo) {
    __nv_bfloat16 hx = __float2bfloat16(x), hy = __float2bfloat16(y);
    __nv_bfloat16 lx = __float2bfloat16(x - __bfloat162float(hx));
    __nv_bfloat16 ly = __float2bfloat16(y - __bfloat162float(hy));
    hi = (uint32_t)__bfloat16_as_ushort(hx) | ((uint32_t)__bfloat16_as_ushort(hy) << 16);
    lo = (uint32_t)__bfloat16_as_ushort(lx) | ((uint32_t)__bfloat16_as_ushort(ly) << 16);
}
__device__ __forceinline__ void cstore(uint32_t* H, uint32_t* L, int i, float4 v) {
    uint32_t h0, l0, h1, l1;
    split2(v.x, v.y, h0, l0);
    split2(v.z, v.w, h1, l1);
    *(uint2*)(H + i) = make_uint2(h0, h1);
    *(uint2*)(L + i) = make_uint2(l0, l1);
}

__device__ __forceinline__ uint32_t smem_u32(const void* p) {
    uint32_t a;
    asm("{ .reg .u64 t; cvta.to.shared.u64 t, %1; cvt.u32.u64 %0, t; }" : "=r"(a) : "l"(p));
    return a;
}
#define CP_ASYNC16(saddr, gptr) \
    asm volatile("cp.async.ca.shared.global [%0], [%1], 16;" :: "r"(saddr), "l"(gptr))
#define CP_COMMIT() asm volatile("cp.async.commit_group;" ::: "memory")
#define CP_WAIT1()  asm volatile("cp.async.wait_group 1;" ::: "memory")
#define CP_WAIT0()  asm volatile("cp.async.wait_group 0;" ::: "memory")

// ---------------- SMEM layout for k_kv (dynamic, 223744 B) ----------------
// bf16 tiles use row stride 40 halves (20 u32) => conflict-free fragment loads.
#define OFF_BK    0
#define OFF_BV    512
#define OFF_DT    1024
#define OFF_FREQ  1536
#define OFF_TB    2048
#define OFF_RAWA  2560                        // [2][128*32] f32 : 2*16384
#define OFF_RAWB  (OFF_RAWA + 32768)          // [2][256*32] f32 : 2*32768
#define OFF_AH    (OFF_RAWB + 65536)          // [2][128*40] bf16: 2*10240
#define OFF_AL    (OFF_AH + 20480)
#define OFF_BH    (OFF_AL + 20480)            // [2][256*40] bf16: 2*20480
#define OFF_BL    (OFF_BH + 40960)
#define KV_SMEM   (OFF_BL + 40960)            // 223744

// ================= fused K+V projection (pipelined mma.sync bf16) =================
// Per CTA: 128 edges, N=256 output ([K|V]), K-dim 384 in 12 chunks of 32.
__global__ void __launch_bounds__(512, 1) k_kv(const float* __restrict__ h,
                                               const float* __restrict__ f,
                                               const float* __restrict__ dt,
                                               const float* __restrict__ freq,
                                               const float* __restrict__ tb,
                                               const float* __restrict__ Wk,
                                               const float* __restrict__ bk,
                                               const float* __restrict__ Wv,
                                               const float* __restrict__ bv,
                                               const int* __restrict__ dst_idx) {
    extern __shared__ char smem[];
    uint32_t sb = smem_u32(smem);
    int tid = threadIdx.x, wid = tid >> 5, lane = tid & 31;
    int e0 = blockIdx.x * 128;

    float* sbk   = (float*)(smem + OFF_BK);
    float* sbv   = (float*)(smem + OFF_BV);
    float* dts   = (float*)(smem + OFF_DT);
    float* freqs = (float*)(smem + OFF_FREQ);
    float* tbs   = (float*)(smem + OFF_TB);
    if (tid < 128) {
        sbk[tid] = bk[tid];
        sbv[tid] = bv[tid];
        dts[tid] = dt[e0 + tid];
        freqs[tid] = freq[tid];
        tbs[tid] = tb[tid];
    }

    // ---- cp.async issue for chunk g into raw[g&1] ----
    auto issue = [&](int g) {
        int s = g & 1;
        if (g < 8) {
            const float* base = (g < 4) ? h + (size_t)(ND + e0) * DD + g * 32
                                        : f + (size_t)e0 * DD + (g - 4) * 32;
#pragma unroll
            for (int r = 0; r < 2; r++) {
                int idx = tid + r * 512;
                int m = idx >> 3, kq = (idx & 7) * 4;
                CP_ASYNC16(sb + OFF_RAWA + s * 16384 + (m * 32 + kq) * 4,
                           base + (size_t)m * DD + kq);
            }
        }
#pragma unroll
        for (int r = 0; r < 4; r++) {
            int idx = tid + r * 512;
            int n = idx >> 3, kq = (idx & 7) * 4;
            const float* src = (n < 128) ? Wk + n * 384 + g * 32 + kq
                                         : Wv + (n - 128) * 384 + g * 32 + kq;
            CP_ASYNC16(sb + OFF_RAWB + s * 32768 + (n * 32 + kq) * 4, src);
        }
        CP_COMMIT();
    };

    // ---- convert chunk cc from raw[cc&1] into bf16 bufs [cc&1] ----
    auto convert = [&](int cc) {
        int s = cc & 1;
        uint32_t* AH = (uint32_t*)(smem + OFF_AH + s * 10240);
        uint32_t* AL = (uint32_t*)(smem + OFF_AL + s * 10240);
        uint32_t* BH = (uint32_t*)(smem + OFF_BH + s * 20480);
        uint32_t* BL = (uint32_t*)(smem + OFF_BL + s * 20480);
        if (cc < 8) {
#pragma unroll
            for (int r = 0; r < 2; r++) {
                int idx = tid + r * 512;
                int m = idx >> 3, kq = (idx & 7) * 4;
                float4 v = *(const float4*)(smem + OFF_RAWA + s * 16384 + (m * 32 + kq) * 4);
                cstore(AH, AL, m * 20 + (kq >> 1), v);
            }
        } else {
#pragma unroll
            for (int r = 0; r < 2; r++) {
                int idx = tid + r * 512;
                int m = idx >> 3, kq = (idx & 7) * 4;
                int ko = (cc - 8) * 32 + kq;
                float d = dts[m];
                float4 v;
                v.x = __cosf(fmaf(d, freqs[ko + 0], tbs[ko + 0]));
                v.y = __cosf(fmaf(d, freqs[ko + 1], tbs[ko + 1]));
                v.z = __cosf(fmaf(d, freqs[ko + 2], tbs[ko + 2]));
                v.w = __cosf(fmaf(d, freqs[ko + 3], tbs[ko + 3]));
                cstore(AH, AL, m * 20 + (kq >> 1), v);
            }
        }
#pragma unroll
        for (int r = 0; r < 4; r++) {
            int idx = tid + r * 512;
            int n = idx >> 3, kq = (idx & 7) * 4;
            float4 v = *(const float4*)(smem + OFF_RAWB + s * 32768 + (n * 32 + kq) * 4);
            cstore(BH, BL, n * 20 + (kq >> 1), v);
        }
    };

    int wm = wid & 3, wn = wid >> 2;      // 4 warps in M x 4 warps in N
    int qr = lane >> 2, qc = (lane & 3) * 2;
    float d[2][8][4];
#pragma unroll
    for (int mt = 0; mt < 2; mt++)
#pragma unroll
        for (int nt = 0; nt < 8; nt++)
#pragma unroll
            for (int j = 0; j < 4; j++) d[mt][nt][j] = 0.f;

    // prologue: chunks 0 and 1 in flight, convert chunk 0
    issue(0);
    issue(1);
    CP_WAIT1();
    __syncthreads();
    convert(0);

    for (int c = 0; c < 12; c++) {
        int s = c & 1, s1 = (c + 1) & 1;
        __syncthreads();                 // convert(c)/MMA(c-1) done before raw[s] reuse
        if (c + 2 <= 11) { issue(c + 2); CP_WAIT1(); }
        else             { CP_WAIT0(); }
        __syncthreads();                 // raw(c+1) visible to all

        if (c + 1 <= 11) convert(c + 1); // overlaps with MMA(c) across warps

        // ---- MMA on chunk c from bf16 bufs [s] ----
        const uint32_t* AH = (const uint32_t*)(smem + OFF_AH + s * 10240);
        const uint32_t* AL = (const uint32_t*)(smem + OFF_AL + s * 10240);
        const uint32_t* BH = (const uint32_t*)(smem + OFF_BH + s * 20480);
        const uint32_t* BL = (const uint32_t*)(smem + OFF_BL + s * 20480);
#pragma unroll
        for (int ks = 0; ks < 2; ks++) {
            int kw = ks * 8 + (lane & 3);   // u32 column within row
            uint32_t bh[8][2], bl[8][2];
#pragma unroll
            for (int nt = 0; nt < 8; nt++) {
                int n = wn * 64 + nt * 8 + qr;
                int i0 = n * 20 + kw;
                bh[nt][0] = BH[i0]; bh[nt][1] = BH[i0 + 4];
                bl[nt][0] = BL[i0]; bl[nt][1] = BL[i0 + 4];
            }
#pragma unroll
            for (int mt = 0; mt < 2; mt++) {
                int rrow = wm * 32 + mt * 16 + qr;
                int i0 = rrow * 20 + kw;
                uint32_t ah[4], al[4];
                ah[0] = AH[i0]; ah[1] = AH[i0 + 160]; ah[2] = AH[i0 + 4]; ah[3] = AH[i0 + 164];
                al[0] = AL[i0]; al[1] = AL[i0 + 160]; al[2] = AL[i0 + 4]; al[3] = AL[i0 + 164];
#pragma unroll
                for (int nt = 0; nt < 8; nt++) {
                    mma_bf16(d[mt][nt], ah, bh[nt]);
                    mma_bf16(d[mt][nt], ah, bl[nt]);
                    mma_bf16(d[mt][nt], al, bh[nt]);
                }
            }
        }
    }

    // ---- epilogue ----
    if (wn < 2) {
        // K cols [wn*64, wn*64+64) -> heads wn*4 .. wn*4+3
#pragma unroll
        for (int mt = 0; mt < 2; mt++) {
#pragma unroll
            for (int hh2 = 0; hh2 < 2; hh2++) {
                int e = e0 + wm * 32 + mt * 16 + qr + hh2 * 8;
                int dsti = dst_idx[e];
                const float* q = &g_Qnodes[(size_t)dsti * DD];
                float part[4] = {0.f, 0.f, 0.f, 0.f};
#pragma unroll
                for (int nt = 0; nt < 8; nt++) {
                    int cc = wn * 64 + nt * 8 + qc;
                    float v0 = d[mt][nt][hh2 * 2 + 0] + sbk[cc];
                    float v1 = d[mt][nt][hh2 * 2 + 1] + sbk[cc + 1];
                    float2 qv = *(const float2*)&q[cc];
                    part[(nt * 8 + qc) >> 4] += v0 * qv.x + v1 * qv.y;
                }
#pragma unroll
                for (int i = 0; i < 4; i++) {
                    part[i] += __shfl_xor_sync(0xffffffffu, part[i], 1);
                    part[i] += __shfl_xor_sync(0xffffffffu, part[i], 2);
                }
                if ((lane & 3) == 0) {
#pragma unroll
                    for (int hh = 0; hh < 4; hh++) {
                        int head = wn * 4 + hh;
                        float p = part[hh];
                        float l = p > 0.f ? p : 0.2f * p;
                        g_logits[(size_t)e * NH + head] = l;
                        unsigned key = __float_as_uint(l);
                        key = (l >= 0.f) ? (key | 0x80000000u) : ~key;
                        atomicMax(&g_segmax[dsti * NH + head], key);
                    }
                }
            }
        }
    } else {
        int cvb = (wn - 2) * 64;
#pragma unroll
        for (int mt = 0; mt < 2; mt++) {
#pragma unroll
            for (int hh2 = 0; hh2 < 2; hh2++) {
                int e = e0 + wm * 32 + mt * 16 + qr + hh2 * 8;
#pragma unroll
                for (int nt = 0; nt < 8; nt++) {
                    int cc = cvb + nt * 8 + qc;
                    float2 o;
                    o.x = d[mt][nt][hh2 * 2 + 0] + sbv[cc];
                    o.y = d[mt][nt][hh2 * 2 + 1] + sbv[cc + 1];
                    *(float2*)&g_V[(size_t)e * DD + cc] = o;
                }
            }
        }
    }
}

// ---------------- segment softmax ----------------
__global__ void k_softmax(const int* __restrict__ dst_idx) {
    int i = blockIdx.x * blockDim.x + threadIdx.x;
    if (i >= NE * NH) return;
    int e = i >> 3, hh = i & 7;
    int dsti = dst_idx[e];
    unsigned key = g_segmax[dsti * NH + hh];
    float m = (key & 0x80000000u) ? __uint_as_float(key & 0x7FFFFFFFu) : __uint_as_float(~key);
    float ex = expf(g_logits[i] - m);
    g_logits[i] = ex;
    atomicAdd(&g_segsum[dsti * NH + hh], ex);
}

// ---------------- weighted aggregation ----------------
__global__ void k_agg(const int* __restrict__ dst_idx) {
    int i = blockIdx.x * blockDim.x + threadIdx.x;
    if (i >= NE * 32) return;
    int e = i >> 5, g = i & 31, hh = g >> 2;
    int dsti = dst_idx[e];
    float att = g_logits[(size_t)e * NH + hh] / g_segsum[dsti * NH + hh];
    float4 v = *(const float4*)&g_V[(size_t)e * DD + g * 4];
    float* p = &g_agg[dsti * DD + g * 4];
    atomicAdd(p + 0, att * v.x);
    atomicAdd(p + 1, att * v.y);
    atomicAdd(p + 2, att * v.z);
    atomicAdd(p + 3, att * v.w);
}

// ---------------- output projection + relu + layernorm ----------------
__global__ void __launch_bounds__(256) k_gemmOut(const float* __restrict__ h,
                                                 const float* __restrict__ Wout,
                                                 const float* __restrict__ bout,
                                                 const float* __restrict__ gam,
                                                 const float* __restrict__ bet,
                                                 float* __restrict__ out) {
    __shared__ float As[32][132];
    __shared__ float Bs[32][132];
    int tid = threadIdx.x, tx = tid & 15, ty = tid >> 4;
    int m0 = blockIdx.x * 128;
    float c[8][8];
#pragma unroll
    for (int i = 0; i < 8; i++)
#pragma unroll
        for (int j = 0; j < 8; j++) c[i][j] = 0.f;

    for (int kc = 0; kc < 256; kc += 32) {
#pragma unroll
        for (int r = 0; r < 16; r++) {
            int t = tid + r * 256;
            int m = t >> 5, k = t & 31;
            int kg = kc + k;
            float v;
            if (kg < 128) v = g_agg[(m0 + m) * DD + kg];
            else v = h[(size_t)(m0 + m) * DD + (kg - 128)];
            As[k][m] = v;
            Bs[k][m] = Wout[m * 256 + kg];
        }
        __syncthreads();
#pragma unroll 8
        for (int k = 0; k < 32; k++) {
            float a[8], b[8];
            *(float4*)&a[0] = *(const float4*)&As[k][ty * 8];
            *(float4*)&a[4] = *(const float4*)&As[k][ty * 8 + 4];
            *(float4*)&b[0] = *(const float4*)&Bs[k][tx * 8];
            *(float4*)&b[4] = *(const float4*)&Bs[k][tx * 8 + 4];
#pragma unroll
            for (int i = 0; i < 8; i++)
#pragma unroll
                for (int j = 0; j < 8; j++) c[i][j] = fmaf(a[i], b[j], c[i][j]);
        }
        __syncthreads();
    }

    float bj[8], gj[8], bb[8];
#pragma unroll
    for (int j = 0; j < 8; j++) {
        int col = tx * 8 + j;
        bj[j] = bout[col];
        gj[j] = gam[col];
        bb[j] = bet[col];
    }
#pragma unroll
    for (int i = 0; i < 8; i++) {
        float x[8];
        float s = 0.f, s2 = 0.f;
#pragma unroll
        for (int j = 0; j < 8; j++) {
            x[j] = fmaxf(c[i][j] + bj[j], 0.f);
            s += x[j];
            s2 += x[j] * x[j];
        }
#pragma unroll
        for (int off = 8; off >= 1; off >>= 1) {
            s  += __shfl_xor_sync(0xffffffffu, s,  off, 16);
            s2 += __shfl_xor_sync(0xffffffffu, s2, off, 16);
        }
        float mu = s * (1.f / 128.f);
        float var = s2 * (1.f / 128.f) - mu * mu;
        float inv = rsqrtf(fmaxf(var, 0.f) + 1e-5f);
        int m = m0 + ty * 8 + i;
#pragma unroll
        for (int jg = 0; jg < 2; jg++) {
            float4 o;
            o.x = (x[jg * 4 + 0] - mu) * inv * gj[jg * 4 + 0] + bb[jg * 4 + 0];
            o.y = (x[jg * 4 + 1] - mu) * inv * gj[jg * 4 + 1] + bb[jg * 4 + 1];
            o.z = (x[jg * 4 + 2] - mu) * inv * gj[jg * 4 + 2] + bb[jg * 4 + 2];
            o.w = (x[jg * 4 + 3] - mu) * inv * gj[jg * 4 + 3] + bb[jg * 4 + 3];
            *(float4*)&out[(size_t)m * DD + tx * 8 + jg * 4] = o;
        }
    }
}

// ---------------- launch ----------------
extern "C" void kernel_launch(void* const* d_in, const int* in_sizes, int n_in,
                              void* d_out, int out_size) {
    const float* h    = (const float*)d_in[0];
    const float* f    = (const float*)d_in[1];
    const float* dt   = (const float*)d_in[2];
    const int*   dst  = (const int*)d_in[3];
    const float* freq = (const float*)d_in[4];
    const float* tb   = (const float*)d_in[5];
    const float* Wq   = (const float*)d_in[6];
    const float* bq   = (const float*)d_in[7];
    const float* Wk   = (const float*)d_in[8];
    const float* bk   = (const float*)d_in[9];
    const float* Wv   = (const float*)d_in[10];
    const float* bv   = (const float*)d_in[11];
    const float* Wout = (const float*)d_in[12];
    const float* bout = (const float*)d_in[13];
    const float* gam  = (const float*)d_in[14];
    const float* bet  = (const float*)d_in[15];
    float* out = (float*)d_out;

    cudaFuncSetAttribute(k_kv, cudaFuncAttributeMaxDynamicSharedMemorySize, KV_SMEM);

    k_init<<<2048, 256>>>();
    k_bqeff<<<1, 128>>>(Wq, bq, tb);
    k_gemmQ<<<ND / 128, 256>>>(h, Wq);
    k_kv<<<NE / 128, 512, KV_SMEM>>>(h, f, dt, freq, tb, Wk, bk, Wv, bv, dst);
    k_softmax<<<(NE * NH) / 256, 256>>>(dst);
    k_agg<<<(NE * 32) / 256, 256>>>(dst);
    k_gemmOut<<<ND / 128, 256>>>(h, Wout, bout, gam, bet, out);
}

// round 5
// speedup vs baseline: 3.6371x; 1.2533x over previous
#include <cuda_runtime.h>
#include <cuda_bf16.h>
#include <cstdint>

#define ND 32768
#define NE 524288
#define DD 128
#define NH 8

// ---------------- scratch (static device memory; no allocations) ----------------
__device__ float    g_Qnodes[(size_t)ND * DD];   // 16 MB
__device__ float    g_V[(size_t)NE * DD];        // 256 MB
__device__ float    g_logits[(size_t)NE * NH];   // 16 MB
__device__ unsigned g_segmax[ND * NH];           // 1 MB
__device__ float    g_segsum[ND * NH];           // 1 MB
__device__ float    g_agg[ND * DD];              // 16 MB
__device__ float    g_bqeff[DD];
// preconverted [Wk;Wv] bf16 hi/lo, chunk-tiled: [12 chunks][256 rows][16 u32]
__device__ uint32_t g_WH[12 * 256 * 16];
__device__ uint32_t g_WL[12 * 256 * 16];

// ---------------- init ----------------
__global__ void k_init() {
    int stride = gridDim.x * blockDim.x;
    int t0 = blockIdx.x * blockDim.x + threadIdx.x;
    for (int i = t0; i < ND * DD; i += stride) g_agg[i] = 0.f;
    for (int i = t0; i < ND * NH; i += stride) { g_segsum[i] = 0.f; g_segmax[i] = 0u; }
}

__global__ void k_bqeff(const float* __restrict__ Wq, const float* __restrict__ bq,
                        const float* __restrict__ tb) {
    int j = threadIdx.x;
    float s = bq[j];
    for (int t = 0; t < DD; t++) s += cosf(tb[t]) * Wq[j * 256 + 128 + t];
    g_bqeff[j] = s;
}

// ======== bf16 hi/lo split helpers ========
__device__ __forceinline__ void split2(float x, float y, uint32_t& hi, uint32_t& lo) {
    __nv_bfloat16 hx = __float2bfloat16(x), hy = __float2bfloat16(y);
    __nv_bfloat16 lx = __float2bfloat16(x - __bfloat162float(hx));
    __nv_bfloat16 ly = __float2bfloat16(y - __bfloat162float(hy));
    hi = (uint32_t)__bfloat16_as_ushort(hx) | ((uint32_t)__bfloat16_as_ushort(hy) << 16);
    lo = (uint32_t)__bfloat16_as_ushort(lx) | ((uint32_t)__bfloat16_as_ushort(ly) << 16);
}
__device__ __forceinline__ void cstore(uint32_t* H, uint32_t* L, int i, float4 v) {
    uint32_t h0, l0, h1, l1;
    split2(v.x, v.y, h0, l0);
    split2(v.z, v.w, h1, l1);
    *(uint2*)(H + i) = make_uint2(h0, h1);
    *(uint2*)(L + i) = make_uint2(l0, l1);
}

// ---------------- weight preconversion (runs once per launch, trivial cost) ----------------
__global__ void k_wconv(const float* __restrict__ Wk, const float* __restrict__ Wv) {
    int i = blockIdx.x * blockDim.x + threadIdx.x;   // 49152 u32 slots
    int c = i >> 12;            // chunk
    int n = (i >> 4) & 255;     // output row ([K|V])
    int q = i & 15;             // u32 slot (2 k-elements)
    int k = c * 32 + q * 2;
    const float* src = (n < 128) ? &Wk[n * 384 + k] : &Wv[(n - 128) * 384 + k];
    uint32_t hi, lo;
    split2(src[0], src[1], hi, lo);
    g_WH[i] = hi;
    g_WL[i] = lo;
}

// ---------------- Q projection (SIMT fp32, small) ----------------
__global__ void __launch_bounds__(256) k_gemmQ(const float* __restrict__ h,
                                               const float* __restrict__ Wq) {
    __shared__ float As[32][132];
    __shared__ float Bs[32][132];
    int tid = threadIdx.x, tx = tid & 15, ty = tid >> 4;
    int m0 = blockIdx.x * 128;
    float c[8][8];
#pragma unroll
    for (int i = 0; i < 8; i++)
#pragma unroll
        for (int j = 0; j < 8; j++) c[i][j] = 0.f;

    for (int kc = 0; kc < 128; kc += 32) {
#pragma unroll
        for (int r = 0; r < 16; r++) {
            int t = tid + r * 256;
            int m = t >> 5, k = t & 31;
            As[k][m] = h[(size_t)(m0 + m) * DD + kc + k];
            Bs[k][m] = Wq[m * 256 + kc + k];
        }
        __syncthreads();
#pragma unroll 8
        for (int k = 0; k < 32; k++) {
            float a[8], b[8];
            *(float4*)&a[0] = *(const float4*)&As[k][ty * 8];
            *(float4*)&a[4] = *(const float4*)&As[k][ty * 8 + 4];
            *(float4*)&b[0] = *(const float4*)&Bs[k][tx * 8];
            *(float4*)&b[4] = *(const float4*)&Bs[k][tx * 8 + 4];
#pragma unroll
            for (int i = 0; i < 8; i++)
#pragma unroll
                for (int j = 0; j < 8; j++) c[i][j] = fmaf(a[i], b[j], c[i][j]);
        }
        __syncthreads();
    }
#pragma unroll
    for (int i = 0; i < 8; i++) {
        int m = m0 + ty * 8 + i;
#pragma unroll
        for (int jg = 0; jg < 2; jg++) {
            float4 o;
            o.x = c[i][jg * 4 + 0] + g_bqeff[tx * 8 + jg * 4 + 0];
            o.y = c[i][jg * 4 + 1] + g_bqeff[tx * 8 + jg * 4 + 1];
            o.z = c[i][jg * 4 + 2] + g_bqeff[tx * 8 + jg * 4 + 2];
            o.w = c[i][jg * 4 + 3] + g_bqeff[tx * 8 + jg * 4 + 3];
            *(float4*)&g_Qnodes[(size_t)m * DD + tx * 8 + jg * 4] = o;
        }
    }
}

// ======== mma.sync / ldmatrix / cp.async primitives ========
__device__ __forceinline__ void mma_bf16(float* d, const uint32_t* a, const uint32_t* b) {
    asm volatile(
        "mma.sync.aligned.m16n8k16.row.col.f32.bf16.bf16.f32 "
        "{%0,%1,%2,%3},{%4,%5,%6,%7},{%8,%9},{%0,%1,%2,%3};"
        : "+f"(d[0]), "+f"(d[1]), "+f"(d[2]), "+f"(d[3])
        : "r"(a[0]), "r"(a[1]), "r"(a[2]), "r"(a[3]), "r"(b[0]), "r"(b[1]));
}
#define LDMX4(r, addr) \
    asm volatile("ldmatrix.sync.aligned.m8n8.x4.shared.b16 {%0,%1,%2,%3}, [%4];" \
        : "=r"((r)[0]), "=r"((r)[1]), "=r"((r)[2]), "=r"((r)[3]) : "r"(addr))

__device__ __forceinline__ uint32_t smem_u32(const void* p) {
    uint32_t a;
    asm("{ .reg .u64 t; cvta.to.shared.u64 t, %1; cvt.u32.u64 %0, t; }" : "=r"(a) : "l"(p));
    return a;
}
#define CP_ASYNC16(saddr, gptr) \
    asm volatile("cp.async.ca.shared.global [%0], [%1], 16;" :: "r"(saddr), "l"(gptr))
#define CP_COMMIT() asm volatile("cp.async.commit_group;" ::: "memory")
#define CP_WAIT1()  asm volatile("cp.async.wait_group 1;" ::: "memory")
#define CP_WAIT0()  asm volatile("cp.async.wait_group 0;" ::: "memory")

// ---------------- SMEM layout for k_kv (dynamic, 125440 B) ----------------
// bf16 tiles: row stride 20 u32 (80 B) -> ldmatrix conflict-free, slots 0..15 used.
#define OFF_BK    0
#define OFF_BV    512
#define OFF_DT    1024
#define OFF_FREQ  1536
#define OFF_TB    2048
#define OFF_AH    2560                        // [2 stages][128*20 u32] = 2*10240
#define OFF_AL    (OFF_AH + 20480)            // 23040
#define OFF_BH    (OFF_AL + 20480)            // 43520: [2 stages][256*20 u32] = 2*20480
#define OFF_BL    (OFF_BH + 40960)            // 84480
#define KV_SMEM   (OFF_BL + 40960)            // 125440

// ================= fused K+V projection (pipelined mma.sync bf16, ldmatrix) =================
__global__ void __launch_bounds__(512, 1) k_kv(const float* __restrict__ h,
                                               const float* __restrict__ f,
                                               const float* __restrict__ dt,
                                               const float* __restrict__ freq,
                                               const float* __restrict__ tb,
                                               const float* __restrict__ bk,
                                               const float* __restrict__ bv,
                                               const int* __restrict__ dst_idx) {
    extern __shared__ char smem[];
    uint32_t sb = smem_u32(smem);
    int tid = threadIdx.x, wid = tid >> 5, lane = tid & 31;
    int e0 = blockIdx.x * 128;

    float* sbk   = (float*)(smem + OFF_BK);
    float* sbv   = (float*)(smem + OFF_BV);
    float* dts   = (float*)(smem + OFF_DT);
    float* freqs = (float*)(smem + OFF_FREQ);
    float* tbs   = (float*)(smem + OFF_TB);
    if (tid < 128) {
        sbk[tid] = bk[tid];
        sbv[tid] = bv[tid];
        dts[tid] = dt[e0 + tid];
        freqs[tid] = freq[tid];
        tbs[tid] = tb[tid];
    }

    // ---- B: cp.async preconverted weights for chunk g into stage g&1 ----
    auto issueB = [&](int g) {
        int s = g & 1;
#pragma unroll
        for (int r = 0; r < 2; r++) {
            int idx = tid + r * 512;
            int n = idx >> 2, q4 = (idx & 3) * 4;
            CP_ASYNC16(sb + OFF_BH + s * 20480 + (n * 20 + q4) * 4,
                       &g_WH[(g * 256 + n) * 16 + q4]);
        }
#pragma unroll
        for (int r = 0; r < 2; r++) {
            int idx = tid + r * 512;
            int n = idx >> 2, q4 = (idx & 3) * 4;
            CP_ASYNC16(sb + OFF_BL + s * 20480 + (n * 20 + q4) * 4,
                       &g_WL[(g * 256 + n) * 16 + q4]);
        }
        CP_COMMIT();
    };

    // ---- A: LDG raw f32 for chunk g (skipped for cos chunks) ----
    auto ldgA = [&](int g, float4* av) {
        if (g < 8) {
            const float* base = (g < 4) ? h + (size_t)(ND + e0) * DD + g * 32
                                        : f + (size_t)e0 * DD + (g - 4) * 32;
#pragma unroll
            for (int r = 0; r < 2; r++) {
                int idx = tid + r * 512;
                int m = idx >> 3, kq = (idx & 7) * 4;
                av[r] = *(const float4*)(base + (size_t)m * DD + kq);
            }
        }
    };
    // ---- A: split to bf16 hi/lo, STS into stage g&1 ----
    auto convA = [&](int g, const float4* av) {
        int s = g & 1;
        uint32_t* AH = (uint32_t*)(smem + OFF_AH + s * 10240);
        uint32_t* AL = (uint32_t*)(smem + OFF_AL + s * 10240);
#pragma unroll
        for (int r = 0; r < 2; r++) {
            int idx = tid + r * 512;
            int m = idx >> 3, kq = (idx & 7) * 4;
            float4 v;
            if (g < 8) v = av[r];
            else {
                int ko = (g - 8) * 32 + kq;
                float d = dts[m];
                v.x = __cosf(fmaf(d, freqs[ko + 0], tbs[ko + 0]));
                v.y = __cosf(fmaf(d, freqs[ko + 1], tbs[ko + 1]));
                v.z = __cosf(fmaf(d, freqs[ko + 2], tbs[ko + 2]));
                v.w = __cosf(fmaf(d, freqs[ko + 3], tbs[ko + 3]));
            }
            cstore(AH, AL, m * 20 + (kq >> 1), v);
        }
    };

    int wm = wid & 3, wn = wid >> 2;      // 4 warps in M x 4 warps in N
    int qr = lane >> 2, qc = (lane & 3) * 2;
    float d[2][8][4];
#pragma unroll
    for (int mt = 0; mt < 2; mt++)
#pragma unroll
        for (int nt = 0; nt < 8; nt++)
#pragma unroll
            for (int j = 0; j < 4; j++) d[mt][nt][j] = 0.f;

    // lane-constant ldmatrix address offsets (bytes)
    uint32_t aoff = (uint32_t)(wm * 32 + (lane & 7) + ((lane >> 3) & 1) * 8) * 80
                  + ((lane >> 4) & 1) * 16;
    uint32_t boff = (uint32_t)(wn * 64 + (lane & 7) + ((lane >> 4) & 1) * 8) * 80
                  + ((lane >> 3) & 1) * 16;

    // ---- prologue ----
    float4 av[2];
    issueB(0);
    issueB(1);
    ldgA(0, av);
    convA(0, av);
    ldgA(1, av);
    CP_WAIT1();
    __syncthreads();   // B(0), A(0), and smem consts visible

    for (int c = 0; c < 12; c++) {
        int s = c & 1;
        if (c + 1 <= 11) convA(c + 1, av);     // into stage s^1 (overlaps MMA below)
        if (c + 2 <= 11) ldgA(c + 2, av);

        // ---- MMA(c) on stage s ----
        uint32_t baseAH = sb + OFF_AH + s * 10240 + aoff;
        uint32_t baseAL = sb + OFF_AL + s * 10240 + aoff;
        uint32_t baseBH = sb + OFF_BH + s * 20480 + boff;
        uint32_t baseBL = sb + OFF_BL + s * 20480 + boff;
#pragma unroll
        for (int ks = 0; ks < 2; ks++) {
            uint32_t ah[2][4], al[2][4];
            LDMX4(ah[0], baseAH + ks * 32);
            LDMX4(ah[1], baseAH + 1280 + ks * 32);   // +16 rows
            LDMX4(al[0], baseAL + ks * 32);
            LDMX4(al[1], baseAL + 1280 + ks * 32);
#pragma unroll
            for (int ntp = 0; ntp < 4; ntp++) {
                uint32_t bh[4], bl[4];
                LDMX4(bh, baseBH + ntp * 1280 + ks * 32);
                LDMX4(bl, baseBL + ntp * 1280 + ks * 32);
#pragma unroll
                for (int mt = 0; mt < 2; mt++) {
                    mma_bf16(d[mt][2 * ntp],     ah[mt], &bh[0]);
                    mma_bf16(d[mt][2 * ntp],     ah[mt], &bl[0]);
                    mma_bf16(d[mt][2 * ntp],     al[mt], &bh[0]);
                    mma_bf16(d[mt][2 * ntp + 1], ah[mt], &bh[2]);
                    mma_bf16(d[mt][2 * ntp + 1], ah[mt], &bl[2]);
                    mma_bf16(d[mt][2 * ntp + 1], al[mt], &bh[2]);
                }
            }
        }
        __syncthreads();                       // stage s free
        if (c + 2 <= 11) { issueB(c + 2); CP_WAIT1(); }
        else if (c + 1 <= 11) { CP_WAIT0(); }
        __syncthreads();                       // B(c+1) + A(c+1) visible
    }

    // ---- epilogue ----
    if (wn < 2) {
        // K cols [wn*64, wn*64+64) -> heads wn*4 .. wn*4+3
#pragma unroll
        for (int mt = 0; mt < 2; mt++) {
#pragma unroll
            for (int hh2 = 0; hh2 < 2; hh2++) {
                int e = e0 + wm * 32 + mt * 16 + qr + hh2 * 8;
                int dsti = dst_idx[e];
                const float* q = &g_Qnodes[(size_t)dsti * DD];
                float part[4] = {0.f, 0.f, 0.f, 0.f};
#pragma unroll
                for (int nt = 0; nt < 8; nt++) {
                    int cc = wn * 64 + nt * 8 + qc;
                    float v0 = d[mt][nt][hh2 * 2 + 0] + sbk[cc];
                    float v1 = d[mt][nt][hh2 * 2 + 1] + sbk[cc + 1];
                    float2 qv = *(const float2*)&q[cc];
                    part[(nt * 8 + qc) >> 4] += v0 * qv.x + v1 * qv.y;
                }
#pragma unroll
                for (int i = 0; i < 4; i++) {
                    part[i] += __shfl_xor_sync(0xffffffffu, part[i], 1);
                    part[i] += __shfl_xor_sync(0xffffffffu, part[i], 2);
                }
                if ((lane & 3) == 0) {
#pragma unroll
                    for (int hh = 0; hh < 4; hh++) {
                        int head = wn * 4 + hh;
                        float p = part[hh];
                        float l = p > 0.f ? p : 0.2f * p;
                        g_logits[(size_t)e * NH + head] = l;
                        unsigned key = __float_as_uint(l);
                        key = (l >= 0.f) ? (key | 0x80000000u) : ~key;
                        atomicMax(&g_segmax[dsti * NH + head], key);
                    }
                }
            }
        }
    } else {
        int cvb = (wn - 2) * 64;
#pragma unroll
        for (int mt = 0; mt < 2; mt++) {
#pragma unroll
            for (int hh2 = 0; hh2 < 2; hh2++) {
                int e = e0 + wm * 32 + mt * 16 + qr + hh2 * 8;
#pragma unroll
                for (int nt = 0; nt < 8; nt++) {
                    int cc = cvb + nt * 8 + qc;
                    float2 o;
                    o.x = d[mt][nt][hh2 * 2 + 0] + sbv[cc];
                    o.y = d[mt][nt][hh2 * 2 + 1] + sbv[cc + 1];
                    *(float2*)&g_V[(size_t)e * DD + cc] = o;
                }
            }
        }
    }
}

// ---------------- segment softmax ----------------
__global__ void k_softmax(const int* __restrict__ dst_idx) {
    int i = blockIdx.x * blockDim.x + threadIdx.x;
    if (i >= NE * NH) return;
    int e = i >> 3, hh = i & 7;
    int dsti = dst_idx[e];
    unsigned key = g_segmax[dsti * NH + hh];
    float m = (key & 0x80000000u) ? __uint_as_float(key & 0x7FFFFFFFu) : __uint_as_float(~key);
    float ex = expf(g_logits[i] - m);
    g_logits[i] = ex;
    atomicAdd(&g_segsum[dsti * NH + hh], ex);
}

// ---------------- weighted aggregation ----------------
__global__ void k_agg(const int* __restrict__ dst_idx) {
    int i = blockIdx.x * blockDim.x + threadIdx.x;
    if (i >= NE * 32) return;
    int e = i >> 5, g = i & 31, hh = g >> 2;
    int dsti = dst_idx[e];
    float att = g_logits[(size_t)e * NH + hh] / g_segsum[dsti * NH + hh];
    float4 v = *(const float4*)&g_V[(size_t)e * DD + g * 4];
    float* p = &g_agg[dsti * DD + g * 4];
    atomicAdd(p + 0, att * v.x);
    atomicAdd(p + 1, att * v.y);
    atomicAdd(p + 2, att * v.z);
    atomicAdd(p + 3, att * v.w);
}

// ---------------- output projection + relu + layernorm ----------------
__global__ void __launch_bounds__(256) k_gemmOut(const float* __restrict__ h,
                                                 const float* __restrict__ Wout,
                                                 const float* __restrict__ bout,
                                                 const float* __restrict__ gam,
                                                 const float* __restrict__ bet,
                                                 float* __restrict__ out) {
    __shared__ float As[32][132];
    __shared__ float Bs[32][132];
    int tid = threadIdx.x, tx = tid & 15, ty = tid >> 4;
    int m0 = blockIdx.x * 128;
    float c[8][8];
#pragma unroll
    for (int i = 0; i < 8; i++)
#pragma unroll
        for (int j = 0; j < 8; j++) c[i][j] = 0.f;

    for (int kc = 0; kc < 256; kc += 32) {
#pragma unroll
        for (int r = 0; r < 16; r++) {
            int t = tid + r * 256;
            int m = t >> 5, k = t & 31;
            int kg = kc + k;
            float v;
            if (kg < 128) v = g_agg[(m0 + m) * DD + kg];
            else v = h[(size_t)(m0 + m) * DD + (kg - 128)];
            As[k][m] = v;
            Bs[k][m] = Wout[m * 256 + kg];
        }
        __syncthreads();
#pragma unroll 8
        for (int k = 0; k < 32; k++) {
            float a[8], b[8];
            *(float4*)&a[0] = *(const float4*)&As[k][ty * 8];
            *(float4*)&a[4] = *(const float4*)&As[k][ty * 8 + 4];
            *(float4*)&b[0] = *(const float4*)&Bs[k][tx * 8];
            *(float4*)&b[4] = *(const float4*)&Bs[k][tx * 8 + 4];
#pragma unroll
            for (int i = 0; i < 8; i++)
#pragma unroll
                for (int j = 0; j < 8; j++) c[i][j] = fmaf(a[i], b[j], c[i][j]);
        }
        __syncthreads();
    }

    float bj[8], gj[8], bb[8];
#pragma unroll
    for (int j = 0; j < 8; j++) {
        int col = tx * 8 + j;
        bj[j] = bout[col];
        gj[j] = gam[col];
        bb[j] = bet[col];
    }
#pragma unroll
    for (int i = 0; i < 8; i++) {
        float x[8];
        float s = 0.f, s2 = 0.f;
#pragma unroll
        for (int j = 0; j < 8; j++) {
            x[j] = fmaxf(c[i][j] + bj[j], 0.f);
            s += x[j];
            s2 += x[j] * x[j];
        }
#pragma unroll
        for (int off = 8; off >= 1; off >>= 1) {
            s  += __shfl_xor_sync(0xffffffffu, s,  off, 16);
            s2 += __shfl_xor_sync(0xffffffffu, s2, off, 16);
        }
        float mu = s * (1.f / 128.f);
        float var = s2 * (1.f / 128.f) - mu * mu;
        float inv = rsqrtf(fmaxf(var, 0.f) + 1e-5f);
        int m = m0 + ty * 8 + i;
#pragma unroll
        for (int jg = 0; jg < 2; jg++) {
            float4 o;
            o.x = (x[jg * 4 + 0] - mu) * inv * gj[jg * 4 + 0] + bb[jg * 4 + 0];
            o.y = (x[jg * 4 + 1] - mu) * inv * gj[jg * 4 + 1] + bb[jg * 4 + 1];
            o.z = (x[jg * 4 + 2] - mu) * inv * gj[jg * 4 + 2] + bb[jg * 4 + 2];
            o.w = (x[jg * 4 + 3] - mu) * inv * gj[jg * 4 + 3] + bb[jg * 4 + 3];
            *(float4*)&out[(size_t)m * DD + tx * 8 + jg * 4] = o;
        }
    }
}

// ---------------- launch ----------------
extern "C" void kernel_launch(void* const* d_in, const int* in_sizes, int n_in,
                              void* d_out, int out_size) {
    const float* h    = (const float*)d_in[0];
    const float* f    = (const float*)d_in[1];
    const float* dt   = (const float*)d_in[2];
    const int*   dst  = (const int*)d_in[3];
    const float* freq = (const float*)d_in[4];
    const float* tb   = (const float*)d_in[5];
    const float* Wq   = (const float*)d_in[6];
    const float* bq   = (const float*)d_in[7];
    const float* Wk   = (const float*)d_in[8];
    const float* bk   = (const float*)d_in[9];
    const float* Wv   = (const float*)d_in[10];
    const float* bv   = (const float*)d_in[11];
    const float* Wout = (const float*)d_in[12];
    const float* bout = (const float*)d_in[13];
    const float* gam  = (const float*)d_in[14];
    const float* bet  = (const float*)d_in[15];
    float* out = (float*)d_out;

    cudaFuncSetAttribute(k_kv, cudaFuncAttributeMaxDynamicSharedMemorySize, KV_SMEM);

    k_init<<<2048, 256>>>();
    k_wconv<<<48, 1024>>>(Wk, Wv);
    k_bqeff<<<1, 128>>>(Wq, bq, tb);
    k_gemmQ<<<ND / 128, 256>>>(h, Wq);
    k_kv<<<NE / 128, 512, KV_SMEM>>>(h, f, dt, freq, tb, bk, bv, dst);
    k_softmax<<<(NE * NH) / 256, 256>>>(dst);
    k_agg<<<(NE * 32) / 256, 256>>>(dst);
    k_gemmOut<<<ND / 128, 256>>>(h, Wout, bout, gam, bet, out);
}

// round 6
// speedup vs baseline: 3.7866x; 1.0411x over previous
#include <cuda_runtime.h>
#include <cuda_bf16.h>
#include <cstdint>

#define ND 32768
#define NE 524288
#define DD 128
#define NH 8

// ---------------- scratch (static device memory; no allocations) ----------------
__device__ float    g_Qnodes[(size_t)ND * DD];   // 16 MB
__device__ float    g_V[(size_t)NE * DD];        // 256 MB
__device__ float    g_logits[(size_t)NE * NH];   // 16 MB
__device__ float    g_agg[ND * DD];              // 16 MB
__device__ float    g_bqeff[DD];
// preconverted [Wk;Wv] bf16 hi/lo, chunk-tiled: [12 chunks][256 rows][16 u32]
__device__ uint32_t g_WH[12 * 256 * 16];
__device__ uint32_t g_WL[12 * 256 * 16];
// CSR edge binning
__device__ int g_cnt[ND];
__device__ int g_off[ND + 1];
__device__ int g_pos[ND];
__device__ int g_elist[NE];

// ---------------- CSR build ----------------
__global__ void k_zero() {
    int i = blockIdx.x * blockDim.x + threadIdx.x;
    if (i < ND) g_cnt[i] = 0;
}
__global__ void k_count(const int* __restrict__ dst_idx) {
    int e = blockIdx.x * blockDim.x + threadIdx.x;
    if (e < NE) atomicAdd(&g_cnt[dst_idx[e]], 1);
}
__global__ void __launch_bounds__(1024) k_scan() {
    __shared__ int ps[1024];
    int t = threadIdx.x;
    int base = t * 32;
    int loc[32];
    int s = 0;
#pragma unroll
    for (int j = 0; j < 32; j++) { loc[j] = s; s += g_cnt[base + j]; }
    ps[t] = s;
    __syncthreads();
    for (int off = 1; off < 1024; off <<= 1) {
        int v = (t >= off) ? ps[t - off] : 0;
        __syncthreads();
        ps[t] += v;
        __syncthreads();
    }
    int excl = (t == 0) ? 0 : ps[t - 1];
#pragma unroll
    for (int j = 0; j < 32; j++) {
        int o = excl + loc[j];
        g_off[base + j] = o;
        g_pos[base + j] = o;
    }
    if (t == 1023) g_off[ND] = ps[1023];
}
__global__ void k_scatter(const int* __restrict__ dst_idx) {
    int e = blockIdx.x * blockDim.x + threadIdx.x;
    if (e < NE) {
        int p = atomicAdd(&g_pos[dst_idx[e]], 1);
        g_elist[p] = e;
    }
}

__global__ void k_bqeff(const float* __restrict__ Wq, const float* __restrict__ bq,
                        const float* __restrict__ tb) {
    int j = threadIdx.x;
    float s = bq[j];
    for (int t = 0; t < DD; t++) s += cosf(tb[t]) * Wq[j * 256 + 128 + t];
    g_bqeff[j] = s;
}

// ======== bf16 hi/lo split helpers ========
__device__ __forceinline__ void split2(float x, float y, uint32_t& hi, uint32_t& lo) {
    __nv_bfloat16 hx = __float2bfloat16(x), hy = __float2bfloat16(y);
    __nv_bfloat16 lx = __float2bfloat16(x - __bfloat162float(hx));
    __nv_bfloat16 ly = __float2bfloat16(y - __bfloat162float(hy));
    hi = (uint32_t)__bfloat16_as_ushort(hx) | ((uint32_t)__bfloat16_as_ushort(hy) << 16);
    lo = (uint32_t)__bfloat16_as_ushort(lx) | ((uint32_t)__bfloat16_as_ushort(ly) << 16);
}
__device__ __forceinline__ void cstore(uint32_t* H, uint32_t* L, int i, float4 v) {
    uint32_t h0, l0, h1, l1;
    split2(v.x, v.y, h0, l0);
    split2(v.z, v.w, h1, l1);
    *(uint2*)(H + i) = make_uint2(h0, h1);
    *(uint2*)(L + i) = make_uint2(l0, l1);
}

// ---------------- weight preconversion ----------------
__global__ void k_wconv(const float* __restrict__ Wk, const float* __restrict__ Wv) {
    int i = blockIdx.x * blockDim.x + threadIdx.x;   // 49152 u32 slots
    int c = i >> 12;
    int n = (i >> 4) & 255;
    int q = i & 15;
    int k = c * 32 + q * 2;
    const float* src = (n < 128) ? &Wk[n * 384 + k] : &Wv[(n - 128) * 384 + k];
    uint32_t hi, lo;
    split2(src[0], src[1], hi, lo);
    g_WH[i] = hi;
    g_WL[i] = lo;
}

// ---------------- Q projection (SIMT fp32, small) ----------------
__global__ void __launch_bounds__(256) k_gemmQ(const float* __restrict__ h,
                                               const float* __restrict__ Wq) {
    __shared__ float As[32][132];
    __shared__ float Bs[32][132];
    int tid = threadIdx.x, tx = tid & 15, ty = tid >> 4;
    int m0 = blockIdx.x * 128;
    float c[8][8];
#pragma unroll
    for (int i = 0; i < 8; i++)
#pragma unroll
        for (int j = 0; j < 8; j++) c[i][j] = 0.f;

    for (int kc = 0; kc < 128; kc += 32) {
#pragma unroll
        for (int r = 0; r < 16; r++) {
            int t = tid + r * 256;
            int m = t >> 5, k = t & 31;
            As[k][m] = h[(size_t)(m0 + m) * DD + kc + k];
            Bs[k][m] = Wq[m * 256 + kc + k];
        }
        __syncthreads();
#pragma unroll 8
        for (int k = 0; k < 32; k++) {
            float a[8], b[8];
            *(float4*)&a[0] = *(const float4*)&As[k][ty * 8];
            *(float4*)&a[4] = *(const float4*)&As[k][ty * 8 + 4];
            *(float4*)&b[0] = *(const float4*)&Bs[k][tx * 8];
            *(float4*)&b[4] = *(const float4*)&Bs[k][tx * 8 + 4];
#pragma unroll
            for (int i = 0; i < 8; i++)
#pragma unroll
                for (int j = 0; j < 8; j++) c[i][j] = fmaf(a[i], b[j], c[i][j]);
        }
        __syncthreads();
    }
#pragma unroll
    for (int i = 0; i < 8; i++) {
        int m = m0 + ty * 8 + i;
#pragma unroll
        for (int jg = 0; jg < 2; jg++) {
            float4 o;
            o.x = c[i][jg * 4 + 0] + g_bqeff[tx * 8 + jg * 4 + 0];
            o.y = c[i][jg * 4 + 1] + g_bqeff[tx * 8 + jg * 4 + 1];
            o.z = c[i][jg * 4 + 2] + g_bqeff[tx * 8 + jg * 4 + 2];
            o.w = c[i][jg * 4 + 3] + g_bqeff[tx * 8 + jg * 4 + 3];
            *(float4*)&g_Qnodes[(size_t)m * DD + tx * 8 + jg * 4] = o;
        }
    }
}

// ======== mma.sync / ldmatrix / cp.async primitives ========
__device__ __forceinline__ void mma_bf16(float* d, const uint32_t* a, const uint32_t* b) {
    asm volatile(
        "mma.sync.aligned.m16n8k16.row.col.f32.bf16.bf16.f32 "
        "{%0,%1,%2,%3},{%4,%5,%6,%7},{%8,%9},{%0,%1,%2,%3};"
        : "+f"(d[0]), "+f"(d[1]), "+f"(d[2]), "+f"(d[3])
        : "r"(a[0]), "r"(a[1]), "r"(a[2]), "r"(a[3]), "r"(b[0]), "r"(b[1]));
}
#define LDMX4(r, addr) \
    asm volatile("ldmatrix.sync.aligned.m8n8.x4.shared.b16 {%0,%1,%2,%3}, [%4];" \
        : "=r"((r)[0]), "=r"((r)[1]), "=r"((r)[2]), "=r"((r)[3]) : "r"(addr))

__device__ __forceinline__ uint32_t smem_u32(const void* p) {
    uint32_t a;
    asm("{ .reg .u64 t; cvta.to.shared.u64 t, %1; cvt.u32.u64 %0, t; }" : "=r"(a) : "l"(p));
    return a;
}
#define CP_ASYNC16(saddr, gptr) \
    asm volatile("cp.async.ca.shared.global [%0], [%1], 16;" :: "r"(saddr), "l"(gptr))
#define CP_COMMIT() asm volatile("cp.async.commit_group;" ::: "memory")
#define CP_WAIT1()  asm volatile("cp.async.wait_group 1;" ::: "memory")
#define CP_WAIT0()  asm volatile("cp.async.wait_group 0;" ::: "memory")

// ---------------- SMEM layout for k_kv (dynamic, 125440 B) ----------------
#define OFF_BK    0
#define OFF_BV    512
#define OFF_DT    1024
#define OFF_FREQ  1536
#define OFF_TB    2048
#define OFF_AH    2560
#define OFF_AL    (OFF_AH + 20480)
#define OFF_BH    (OFF_AL + 20480)
#define OFF_BL    (OFF_BH + 40960)
#define KV_SMEM   (OFF_BL + 40960)            // 125440

// ================= fused K+V projection (pipelined mma.sync bf16, ldmatrix) =================
__global__ void __launch_bounds__(512, 1) k_kv(const float* __restrict__ h,
                                               const float* __restrict__ f,
                                               const float* __restrict__ dt,
                                               const float* __restrict__ freq,
                                               const float* __restrict__ tb,
                                               const float* __restrict__ bk,
                                               const float* __restrict__ bv,
                                               const int* __restrict__ dst_idx) {
    extern __shared__ char smem[];
    uint32_t sb = smem_u32(smem);
    int tid = threadIdx.x, wid = tid >> 5, lane = tid & 31;
    int e0 = blockIdx.x * 128;

    float* sbk   = (float*)(smem + OFF_BK);
    float* sbv   = (float*)(smem + OFF_BV);
    float* dts   = (float*)(smem + OFF_DT);
    float* freqs = (float*)(smem + OFF_FREQ);
    float* tbs   = (float*)(smem + OFF_TB);
    if (tid < 128) {
        sbk[tid] = bk[tid];
        sbv[tid] = bv[tid];
        dts[tid] = dt[e0 + tid];
        freqs[tid] = freq[tid];
        tbs[tid] = tb[tid];
    }

    auto issueB = [&](int g) {
        int s = g & 1;
#pragma unroll
        for (int r = 0; r < 2; r++) {
            int idx = tid + r * 512;
            int n = idx >> 2, q4 = (idx & 3) * 4;
            CP_ASYNC16(sb + OFF_BH + s * 20480 + (n * 20 + q4) * 4,
                       &g_WH[(g * 256 + n) * 16 + q4]);
        }
#pragma unroll
        for (int r = 0; r < 2; r++) {
            int idx = tid + r * 512;
            int n = idx >> 2, q4 = (idx & 3) * 4;
            CP_ASYNC16(sb + OFF_BL + s * 20480 + (n * 20 + q4) * 4,
                       &g_WL[(g * 256 + n) * 16 + q4]);
        }
        CP_COMMIT();
    };

    auto ldgA = [&](int g, float4* av) {
        if (g < 8) {
            const float* base = (g < 4) ? h + (size_t)(ND + e0) * DD + g * 32
                                        : f + (size_t)e0 * DD + (g - 4) * 32;
#pragma unroll
            for (int r = 0; r < 2; r++) {
                int idx = tid + r * 512;
                int m = idx >> 3, kq = (idx & 7) * 4;
                av[r] = *(const float4*)(base + (size_t)m * DD + kq);
            }
        }
    };
    auto convA = [&](int g, const float4* av) {
        int s = g & 1;
        uint32_t* AH = (uint32_t*)(smem + OFF_AH + s * 10240);
        uint32_t* AL = (uint32_t*)(smem + OFF_AL + s * 10240);
#pragma unroll
        for (int r = 0; r < 2; r++) {
            int idx = tid + r * 512;
            int m = idx >> 3, kq = (idx & 7) * 4;
            float4 v;
            if (g < 8) v = av[r];
            else {
                int ko = (g - 8) * 32 + kq;
                float d = dts[m];
                v.x = __cosf(fmaf(d, freqs[ko + 0], tbs[ko + 0]));
                v.y = __cosf(fmaf(d, freqs[ko + 1], tbs[ko + 1]));
                v.z = __cosf(fmaf(d, freqs[ko + 2], tbs[ko + 2]));
                v.w = __cosf(fmaf(d, freqs[ko + 3], tbs[ko + 3]));
            }
            cstore(AH, AL, m * 20 + (kq >> 1), v);
        }
    };

    int wm = wid & 3, wn = wid >> 2;
    int qr = lane >> 2, qc = (lane & 3) * 2;
    float d[2][8][4];
#pragma unroll
    for (int mt = 0; mt < 2; mt++)
#pragma unroll
        for (int nt = 0; nt < 8; nt++)
#pragma unroll
            for (int j = 0; j < 4; j++) d[mt][nt][j] = 0.f;

    uint32_t aoff = (uint32_t)(wm * 32 + (lane & 7) + ((lane >> 3) & 1) * 8) * 80
                  + ((lane >> 4) & 1) * 16;
    uint32_t boff = (uint32_t)(wn * 64 + (lane & 7) + ((lane >> 4) & 1) * 8) * 80
                  + ((lane >> 3) & 1) * 16;

    float4 av[2];
    issueB(0);
    issueB(1);
    ldgA(0, av);
    convA(0, av);
    ldgA(1, av);
    CP_WAIT1();
    __syncthreads();

    for (int c = 0; c < 12; c++) {
        int s = c & 1;
        if (c + 1 <= 11) convA(c + 1, av);
        if (c + 2 <= 11) ldgA(c + 2, av);

        uint32_t baseAH = sb + OFF_AH + s * 10240 + aoff;
        uint32_t baseAL = sb + OFF_AL + s * 10240 + aoff;
        uint32_t baseBH = sb + OFF_BH + s * 20480 + boff;
        uint32_t baseBL = sb + OFF_BL + s * 20480 + boff;
#pragma unroll
        for (int ks = 0; ks < 2; ks++) {
            uint32_t ah[2][4], al[2][4];
            LDMX4(ah[0], baseAH + ks * 32);
            LDMX4(ah[1], baseAH + 1280 + ks * 32);
            LDMX4(al[0], baseAL + ks * 32);
            LDMX4(al[1], baseAL + 1280 + ks * 32);
#pragma unroll
            for (int ntp = 0; ntp < 4; ntp++) {
                uint32_t bh[4], bl[4];
                LDMX4(bh, baseBH + ntp * 1280 + ks * 32);
                LDMX4(bl, baseBL + ntp * 1280 + ks * 32);
#pragma unroll
                for (int mt = 0; mt < 2; mt++) {
                    mma_bf16(d[mt][2 * ntp],     ah[mt], &bh[0]);
                    mma_bf16(d[mt][2 * ntp],     ah[mt], &bl[0]);
                    mma_bf16(d[mt][2 * ntp],     al[mt], &bh[0]);
                    mma_bf16(d[mt][2 * ntp + 1], ah[mt], &bh[2]);
                    mma_bf16(d[mt][2 * ntp + 1], ah[mt], &bl[2]);
                    mma_bf16(d[mt][2 * ntp + 1], al[mt], &bh[2]);
                }
            }
        }
        __syncthreads();
        if (c + 2 <= 11) { issueB(c + 2); CP_WAIT1(); }
        else if (c + 1 <= 11) { CP_WAIT0(); }
        __syncthreads();
    }

    // ---- epilogue: K warps write logits; V warps write V ----
    if (wn < 2) {
#pragma unroll
        for (int mt = 0; mt < 2; mt++) {
#pragma unroll
            for (int hh2 = 0; hh2 < 2; hh2++) {
                int e = e0 + wm * 32 + mt * 16 + qr + hh2 * 8;
                int dsti = dst_idx[e];
                const float* q = &g_Qnodes[(size_t)dsti * DD];
                float part[4] = {0.f, 0.f, 0.f, 0.f};
#pragma unroll
                for (int nt = 0; nt < 8; nt++) {
                    int cc = wn * 64 + nt * 8 + qc;
                    float v0 = d[mt][nt][hh2 * 2 + 0] + sbk[cc];
                    float v1 = d[mt][nt][hh2 * 2 + 1] + sbk[cc + 1];
                    float2 qv = *(const float2*)&q[cc];
                    part[(nt * 8 + qc) >> 4] += v0 * qv.x + v1 * qv.y;
                }
#pragma unroll
                for (int i = 0; i < 4; i++) {
                    part[i] += __shfl_xor_sync(0xffffffffu, part[i], 1);
                    part[i] += __shfl_xor_sync(0xffffffffu, part[i], 2);
                }
                if ((lane & 3) == 0) {
#pragma unroll
                    for (int hh = 0; hh < 4; hh++) {
                        int head = wn * 4 + hh;
                        float p = part[hh];
                        float l = p > 0.f ? p : 0.2f * p;
                        g_logits[(size_t)e * NH + head] = l;
                    }
                }
            }
        }
    } else {
        int cvb = (wn - 2) * 64;
#pragma unroll
        for (int mt = 0; mt < 2; mt++) {
#pragma unroll
            for (int hh2 = 0; hh2 < 2; hh2++) {
                int e = e0 + wm * 32 + mt * 16 + qr + hh2 * 8;
#pragma unroll
                for (int nt = 0; nt < 8; nt++) {
                    int cc = cvb + nt * 8 + qc;
                    float2 o;
                    o.x = d[mt][nt][hh2 * 2 + 0] + sbv[cc];
                    o.y = d[mt][nt][hh2 * 2 + 1] + sbv[cc + 1];
                    *(float2*)&g_V[(size_t)e * DD + cc] = o;
                }
            }
        }
    }
}

// ---------------- per-node softmax + aggregation (warp per dst node, no atomics) ----------------
__global__ void __launch_bounds__(256) k_node() {
    int n = blockIdx.x * 8 + (threadIdx.x >> 5);
    int lane = threadIdx.x & 31;
    int beg = g_off[n], end = g_off[n + 1];

    // pass 1: per-head max
    float mx[NH];
#pragma unroll
    for (int hh = 0; hh < NH; hh++) mx[hh] = -1e30f;
    for (int i = beg + lane; i < end; i += 32) {
        int e = g_elist[i];
        float4 l0 = *(const float4*)&g_logits[(size_t)e * NH];
        float4 l1 = *(const float4*)&g_logits[(size_t)e * NH + 4];
        mx[0] = fmaxf(mx[0], l0.x); mx[1] = fmaxf(mx[1], l0.y);
        mx[2] = fmaxf(mx[2], l0.z); mx[3] = fmaxf(mx[3], l0.w);
        mx[4] = fmaxf(mx[4], l1.x); mx[5] = fmaxf(mx[5], l1.y);
        mx[6] = fmaxf(mx[6], l1.z); mx[7] = fmaxf(mx[7], l1.w);
    }
#pragma unroll
    for (int hh = 0; hh < NH; hh++)
#pragma unroll
        for (int off = 16; off >= 1; off >>= 1)
            mx[hh] = fmaxf(mx[hh], __shfl_xor_sync(0xffffffffu, mx[hh], off));

    // pass 2: per-head sum of exp
    float sm[NH];
#pragma unroll
    for (int hh = 0; hh < NH; hh++) sm[hh] = 0.f;
    for (int i = beg + lane; i < end; i += 32) {
        int e = g_elist[i];
        float4 l0 = *(const float4*)&g_logits[(size_t)e * NH];
        float4 l1 = *(const float4*)&g_logits[(size_t)e * NH + 4];
        sm[0] += expf(l0.x - mx[0]); sm[1] += expf(l0.y - mx[1]);
        sm[2] += expf(l0.z - mx[2]); sm[3] += expf(l0.w - mx[3]);
        sm[4] += expf(l1.x - mx[4]); sm[5] += expf(l1.y - mx[5]);
        sm[6] += expf(l1.z - mx[6]); sm[7] += expf(l1.w - mx[7]);
    }
#pragma unroll
    for (int hh = 0; hh < NH; hh++)
#pragma unroll
        for (int off = 16; off >= 1; off >>= 1)
            sm[hh] += __shfl_xor_sync(0xffffffffu, sm[hh], off);

    // pass 3: weighted V accumulation. lane owns cols [lane*4, lane*4+4), head = lane>>2
    int head = lane >> 2;
    float mh = mx[head];
    float ish = (sm[head] > 0.f) ? 1.f / sm[head] : 0.f;
    float4 acc = make_float4(0.f, 0.f, 0.f, 0.f);
    for (int i = beg; i < end; i++) {
        int e = __ldg(&g_elist[i]);
        float att = expf(g_logits[(size_t)e * NH + head] - mh) * ish;
        float4 v = *(const float4*)&g_V[(size_t)e * DD + lane * 4];
        acc.x = fmaf(att, v.x, acc.x);
        acc.y = fmaf(att, v.y, acc.y);
        acc.z = fmaf(att, v.z, acc.z);
        acc.w = fmaf(att, v.w, acc.w);
    }
    *(float4*)&g_agg[n * DD + lane * 4] = acc;
}

// ---------------- output projection + relu + layernorm ----------------
__global__ void __launch_bounds__(256) k_gemmOut(const float* __restrict__ h,
                                                 const float* __restrict__ Wout,
                                                 const float* __restrict__ bout,
                                                 const float* __restrict__ gam,
                                                 const float* __restrict__ bet,
                                                 float* __restrict__ out) {
    __shared__ float As[32][132];
    __shared__ float Bs[32][132];
    int tid = threadIdx.x, tx = tid & 15, ty = tid >> 4;
    int m0 = blockIdx.x * 128;
    float c[8][8];
#pragma unroll
    for (int i = 0; i < 8; i++)
#pragma unroll
        for (int j = 0; j < 8; j++) c[i][j] = 0.f;

    for (int kc = 0; kc < 256; kc += 32) {
#pragma unroll
        for (int r = 0; r < 16; r++) {
            int t = tid + r * 256;
            int m = t >> 5, k = t & 31;
            int kg = kc + k;
            float v;
            if (kg < 128) v = g_agg[(m0 + m) * DD + kg];
            else v = h[(size_t)(m0 + m) * DD + (kg - 128)];
            As[k][m] = v;
            Bs[k][m] = Wout[m * 256 + kg];
        }
        __syncthreads();
#pragma unroll 8
        for (int k = 0; k < 32; k++) {
            float a[8], b[8];
            *(float4*)&a[0] = *(const float4*)&As[k][ty * 8];
            *(float4*)&a[4] = *(const float4*)&As[k][ty * 8 + 4];
            *(float4*)&b[0] = *(const float4*)&Bs[k][tx * 8];
            *(float4*)&b[4] = *(const float4*)&Bs[k][tx * 8 + 4];
#pragma unroll
            for (int i = 0; i < 8; i++)
#pragma unroll
                for (int j = 0; j < 8; j++) c[i][j] = fmaf(a[i], b[j], c[i][j]);
        }
        __syncthreads();
    }

    float bj[8], gj[8], bb[8];
#pragma unroll
    for (int j = 0; j < 8; j++) {
        int col = tx * 8 + j;
        bj[j] = bout[col];
        gj[j] = gam[col];
        bb[j] = bet[col];
    }
#pragma unroll
    for (int i = 0; i < 8; i++) {
        float x[8];
        float s = 0.f, s2 = 0.f;
#pragma unroll
        for (int j = 0; j < 8; j++) {
            x[j] = fmaxf(c[i][j] + bj[j], 0.f);
            s += x[j];
            s2 += x[j] * x[j];
        }
#pragma unroll
        for (int off = 8; off >= 1; off >>= 1) {
            s  += __shfl_xor_sync(0xffffffffu, s,  off, 16);
            s2 += __shfl_xor_sync(0xffffffffu, s2, off, 16);
        }
        float mu = s * (1.f / 128.f);
        float var = s2 * (1.f / 128.f) - mu * mu;
        float inv = rsqrtf(fmaxf(var, 0.f) + 1e-5f);
        int m = m0 + ty * 8 + i;
#pragma unroll
        for (int jg = 0; jg < 2; jg++) {
            float4 o;
            o.x = (x[jg * 4 + 0] - mu) * inv * gj[jg * 4 + 0] + bb[jg * 4 + 0];
            o.y = (x[jg * 4 + 1] - mu) * inv * gj[jg * 4 + 1] + bb[jg * 4 + 1];
            o.z = (x[jg * 4 + 2] - mu) * inv * gj[jg * 4 + 2] + bb[jg * 4 + 2];
            o.w = (x[jg * 4 + 3] - mu) * inv * gj[jg * 4 + 3] + bb[jg * 4 + 3];
            *(float4*)&out[(size_t)m * DD + tx * 8 + jg * 4] = o;
        }
    }
}

// ---------------- launch ----------------
extern "C" void kernel_launch(void* const* d_in, const int* in_sizes, int n_in,
                              void* d_out, int out_size) {
    const float* h    = (const float*)d_in[0];
    const float* f    = (const float*)d_in[1];
    const float* dt   = (const float*)d_in[2];
    const int*   dst  = (const int*)d_in[3];
    const float* freq = (const float*)d_in[4];
    const float* tb   = (const float*)d_in[5];
    const float* Wq   = (const float*)d_in[6];
    const float* bq   = (const float*)d_in[7];
    const float* Wk   = (const float*)d_in[8];
    const float* bk   = (const float*)d_in[9];
    const float* Wv   = (const float*)d_in[10];
    const float* bv   = (const float*)d_in[11];
    const float* Wout = (const float*)d_in[12];
    const float* bout = (const float*)d_in[13];
    const float* gam  = (const float*)d_in[14];
    const float* bet  = (const float*)d_in[15];
    float* out = (float*)d_out;

    cudaFuncSetAttribute(k_kv, cudaFuncAttributeMaxDynamicSharedMemorySize, KV_SMEM);

    k_wconv<<<48, 1024>>>(Wk, Wv);
    k_bqeff<<<1, 128>>>(Wq, bq, tb);
    k_zero<<<ND / 256, 256>>>();
    k_count<<<NE / 256, 256>>>(dst);
    k_scan<<<1, 1024>>>();
    k_scatter<<<NE / 256, 256>>>(dst);
    k_gemmQ<<<ND / 128, 256>>>(h, Wq);
    k_kv<<<NE / 128, 512, KV_SMEM>>>(h, f, dt, freq, tb, bk, bv, dst);
    k_node<<<ND / 8, 256>>>();
    k_gemmOut<<<ND / 128, 256>>>(h, Wout, bout, gam, bet, out);
}

// round 7
// speedup vs baseline: 4.6557x; 1.2295x over previous
#include <cuda_runtime.h>
#include <cuda_fp16.h>
#include <cstdint>

#define ND 32768
#define NE 524288
#define DD 128
#define NH 8

// ---------------- scratch (static device memory; no allocations) ----------------
__device__ float    g_Qnodes[(size_t)ND * DD];   // 16 MB
__device__ float    g_V[(size_t)NE * DD];        // 256 MB
__device__ float    g_logits[(size_t)NE * NH];   // 16 MB
__device__ float    g_agg[ND * DD];              // 16 MB
__device__ float    g_bqeff[DD];
// preconverted [Wk;Wv] fp16, chunk-tiled: [12 chunks][256 rows][16 u32]
__device__ uint32_t g_WH[12 * 256 * 16];
// CSR edge binning
__device__ int g_cnt[ND];
__device__ int g_off[ND + 1];
__device__ int g_pos[ND];
__device__ int g_elist[NE];

// ---------------- CSR build ----------------
__global__ void k_zero() {
    int i = blockIdx.x * blockDim.x + threadIdx.x;
    if (i < ND) g_cnt[i] = 0;
}
__global__ void k_count(const int* __restrict__ dst_idx) {
    int e = blockIdx.x * blockDim.x + threadIdx.x;
    if (e < NE) atomicAdd(&g_cnt[dst_idx[e]], 1);
}
__global__ void __launch_bounds__(1024) k_scan() {
    __shared__ int ps[1024];
    int t = threadIdx.x;
    int base = t * 32;
    int loc[32];
    int s = 0;
#pragma unroll
    for (int j = 0; j < 32; j++) { loc[j] = s; s += g_cnt[base + j]; }
    ps[t] = s;
    __syncthreads();
    for (int off = 1; off < 1024; off <<= 1) {
        int v = (t >= off) ? ps[t - off] : 0;
        __syncthreads();
        ps[t] += v;
        __syncthreads();
    }
    int excl = (t == 0) ? 0 : ps[t - 1];
#pragma unroll
    for (int j = 0; j < 32; j++) {
        int o = excl + loc[j];
        g_off[base + j] = o;
        g_pos[base + j] = o;
    }
    if (t == 1023) g_off[ND] = ps[1023];
}
__global__ void k_scatter(const int* __restrict__ dst_idx) {
    int e = blockIdx.x * blockDim.x + threadIdx.x;
    if (e < NE) {
        int p = atomicAdd(&g_pos[dst_idx[e]], 1);
        g_elist[p] = e;
    }
}

__global__ void k_bqeff(const float* __restrict__ Wq, const float* __restrict__ bq,
                        const float* __restrict__ tb) {
    int j = threadIdx.x;
    float s = bq[j];
    for (int t = 0; t < DD; t++) s += cosf(tb[t]) * Wq[j * 256 + 128 + t];
    g_bqeff[j] = s;
}

// ======== fp16 split helpers ========
// A path: hi/lo split (hi+lo represents fp32 to ~2^-22)
__device__ __forceinline__ void split2h(float x, float y, uint32_t& hi, uint32_t& lo) {
    __half hx = __float2half_rn(x), hy = __float2half_rn(y);
    __half lx = __float2half_rn(x - __half2float(hx));
    __half ly = __float2half_rn(y - __half2float(hy));
    hi = (uint32_t)__half_as_ushort(hx) | ((uint32_t)__half_as_ushort(hy) << 16);
    lo = (uint32_t)__half_as_ushort(lx) | ((uint32_t)__half_as_ushort(ly) << 16);
}
__device__ __forceinline__ void cstore(uint32_t* H, uint32_t* L, int i, float4 v) {
    uint32_t h0, l0, h1, l1;
    split2h(v.x, v.y, h0, l0);
    split2h(v.z, v.w, h1, l1);
    *(uint2*)(H + i) = make_uint2(h0, h1);
    *(uint2*)(L + i) = make_uint2(l0, l1);
}

// ---------------- weight preconversion: single fp16 ----------------
__global__ void k_wconv(const float* __restrict__ Wk, const float* __restrict__ Wv) {
    int i = blockIdx.x * blockDim.x + threadIdx.x;   // 49152 u32 slots
    int c = i >> 12;
    int n = (i >> 4) & 255;
    int q = i & 15;
    int k = c * 32 + q * 2;
    const float* src = (n < 128) ? &Wk[n * 384 + k] : &Wv[(n - 128) * 384 + k];
    __half h0 = __float2half_rn(src[0]), h1 = __float2half_rn(src[1]);
    g_WH[i] = (uint32_t)__half_as_ushort(h0) | ((uint32_t)__half_as_ushort(h1) << 16);
}

// ---------------- Q projection (SIMT fp32, small) ----------------
__global__ void __launch_bounds__(256) k_gemmQ(const float* __restrict__ h,
                                               const float* __restrict__ Wq) {
    __shared__ float As[32][132];
    __shared__ float Bs[32][132];
    int tid = threadIdx.x, tx = tid & 15, ty = tid >> 4;
    int m0 = blockIdx.x * 128;
    float c[8][8];
#pragma unroll
    for (int i = 0; i < 8; i++)
#pragma unroll
        for (int j = 0; j < 8; j++) c[i][j] = 0.f;

    for (int kc = 0; kc < 128; kc += 32) {
#pragma unroll
        for (int r = 0; r < 16; r++) {
            int t = tid + r * 256;
            int m = t >> 5, k = t & 31;
            As[k][m] = h[(size_t)(m0 + m) * DD + kc + k];
            Bs[k][m] = Wq[m * 256 + kc + k];
        }
        __syncthreads();
#pragma unroll 8
        for (int k = 0; k < 32; k++) {
            float a[8], b[8];
            *(float4*)&a[0] = *(const float4*)&As[k][ty * 8];
            *(float4*)&a[4] = *(const float4*)&As[k][ty * 8 + 4];
            *(float4*)&b[0] = *(const float4*)&Bs[k][tx * 8];
            *(float4*)&b[4] = *(const float4*)&Bs[k][tx * 8 + 4];
#pragma unroll
            for (int i = 0; i < 8; i++)
#pragma unroll
                for (int j = 0; j < 8; j++) c[i][j] = fmaf(a[i], b[j], c[i][j]);
        }
        __syncthreads();
    }
#pragma unroll
    for (int i = 0; i < 8; i++) {
        int m = m0 + ty * 8 + i;
#pragma unroll
        for (int jg = 0; jg < 2; jg++) {
            float4 o;
            o.x = c[i][jg * 4 + 0] + g_bqeff[tx * 8 + jg * 4 + 0];
            o.y = c[i][jg * 4 + 1] + g_bqeff[tx * 8 + jg * 4 + 1];
            o.z = c[i][jg * 4 + 2] + g_bqeff[tx * 8 + jg * 4 + 2];
            o.w = c[i][jg * 4 + 3] + g_bqeff[tx * 8 + jg * 4 + 3];
            *(float4*)&g_Qnodes[(size_t)m * DD + tx * 8 + jg * 4] = o;
        }
    }
}

// ======== mma.sync / ldmatrix / cp.async primitives ========
__device__ __forceinline__ void mma_f16(float* d, const uint32_t* a, const uint32_t* b) {
    asm volatile(
        "mma.sync.aligned.m16n8k16.row.col.f32.f16.f16.f32 "
        "{%0,%1,%2,%3},{%4,%5,%6,%7},{%8,%9},{%0,%1,%2,%3};"
        : "+f"(d[0]), "+f"(d[1]), "+f"(d[2]), "+f"(d[3])
        : "r"(a[0]), "r"(a[1]), "r"(a[2]), "r"(a[3]), "r"(b[0]), "r"(b[1]));
}
#define LDMX4(r, addr) \
    asm volatile("ldmatrix.sync.aligned.m8n8.x4.shared.b16 {%0,%1,%2,%3}, [%4];" \
        : "=r"((r)[0]), "=r"((r)[1]), "=r"((r)[2]), "=r"((r)[3]) : "r"(addr))

__device__ __forceinline__ uint32_t smem_u32(const void* p) {
    uint32_t a;
    asm("{ .reg .u64 t; cvta.to.shared.u64 t, %1; cvt.u32.u64 %0, t; }" : "=r"(a) : "l"(p));
    return a;
}
#define CP_ASYNC16(saddr, gptr) \
    asm volatile("cp.async.ca.shared.global [%0], [%1], 16;" :: "r"(saddr), "l"(gptr))
#define CP_COMMIT() asm volatile("cp.async.commit_group;" ::: "memory")
#define CP_WAIT1()  asm volatile("cp.async.wait_group 1;" ::: "memory")
#define CP_WAIT0()  asm volatile("cp.async.wait_group 0;" ::: "memory")

// ---------------- SMEM layout for k_kv (dynamic, 84480 B) ----------------
// tiles: row stride 20 u32 (80 B) -> ldmatrix conflict-free, slots 0..15 used.
#define OFF_BK    0
#define OFF_BV    512
#define OFF_DT    1024
#define OFF_FREQ  1536
#define OFF_TB    2048
#define OFF_AH    2560                        // [2 stages][128*20 u32] = 2*10240
#define OFF_AL    (OFF_AH + 20480)            // 23040
#define OFF_BH    (OFF_AL + 20480)            // 43520: [2 stages][256*20 u32] = 2*20480
#define KV_SMEM   (OFF_BH + 40960)            // 84480

// ================= fused K+V projection (pipelined mma.sync fp16, 2-product) =================
__global__ void __launch_bounds__(512, 1) k_kv(const float* __restrict__ h,
                                               const float* __restrict__ f,
                                               const float* __restrict__ dt,
                                               const float* __restrict__ freq,
                                               const float* __restrict__ tb,
                                               const float* __restrict__ bk,
                                               const float* __restrict__ bv,
                                               const int* __restrict__ dst_idx) {
    extern __shared__ char smem[];
    uint32_t sb = smem_u32(smem);
    int tid = threadIdx.x, wid = tid >> 5, lane = tid & 31;
    int e0 = blockIdx.x * 128;

    float* sbk   = (float*)(smem + OFF_BK);
    float* sbv   = (float*)(smem + OFF_BV);
    float* dts   = (float*)(smem + OFF_DT);
    float* freqs = (float*)(smem + OFF_FREQ);
    float* tbs   = (float*)(smem + OFF_TB);
    if (tid < 128) {
        sbk[tid] = bk[tid];
        sbv[tid] = bv[tid];
        dts[tid] = dt[e0 + tid];
        freqs[tid] = freq[tid];
        tbs[tid] = tb[tid];
    }

    auto issueB = [&](int g) {
        int s = g & 1;
#pragma unroll
        for (int r = 0; r < 2; r++) {
            int idx = tid + r * 512;
            int n = idx >> 2, q4 = (idx & 3) * 4;
            CP_ASYNC16(sb + OFF_BH + s * 20480 + (n * 20 + q4) * 4,
                       &g_WH[(g * 256 + n) * 16 + q4]);
        }
        CP_COMMIT();
    };

    auto ldgA = [&](int g, float4* av) {
        if (g < 8) {
            const float* base = (g < 4) ? h + (size_t)(ND + e0) * DD + g * 32
                                        : f + (size_t)e0 * DD + (g - 4) * 32;
#pragma unroll
            for (int r = 0; r < 2; r++) {
                int idx = tid + r * 512;
                int m = idx >> 3, kq = (idx & 7) * 4;
                av[r] = *(const float4*)(base + (size_t)m * DD + kq);
            }
        }
    };
    auto convA = [&](int g, const float4* av) {
        int s = g & 1;
        uint32_t* AH = (uint32_t*)(smem + OFF_AH + s * 10240);
        uint32_t* AL = (uint32_t*)(smem + OFF_AL + s * 10240);
#pragma unroll
        for (int r = 0; r < 2; r++) {
            int idx = tid + r * 512;
            int m = idx >> 3, kq = (idx & 7) * 4;
            float4 v;
            if (g < 8) v = av[r];
            else {
                int ko = (g - 8) * 32 + kq;
                float d = dts[m];
                v.x = __cosf(fmaf(d, freqs[ko + 0], tbs[ko + 0]));
                v.y = __cosf(fmaf(d, freqs[ko + 1], tbs[ko + 1]));
                v.z = __cosf(fmaf(d, freqs[ko + 2], tbs[ko + 2]));
                v.w = __cosf(fmaf(d, freqs[ko + 3], tbs[ko + 3]));
            }
            cstore(AH, AL, m * 20 + (kq >> 1), v);
        }
    };

    int wm = wid & 3, wn = wid >> 2;
    int qr = lane >> 2, qc = (lane & 3) * 2;
    float d[2][8][4];
#pragma unroll
    for (int mt = 0; mt < 2; mt++)
#pragma unroll
        for (int nt = 0; nt < 8; nt++)
#pragma unroll
            for (int j = 0; j < 4; j++) d[mt][nt][j] = 0.f;

    uint32_t aoff = (uint32_t)(wm * 32 + (lane & 7) + ((lane >> 3) & 1) * 8) * 80
                  + ((lane >> 4) & 1) * 16;
    uint32_t boff = (uint32_t)(wn * 64 + (lane & 7) + ((lane >> 4) & 1) * 8) * 80
                  + ((lane >> 3) & 1) * 16;

    float4 av[2];
    issueB(0);
    issueB(1);
    ldgA(0, av);
    convA(0, av);
    ldgA(1, av);
    CP_WAIT1();
    __syncthreads();

    for (int c = 0; c < 12; c++) {
        int s = c & 1;
        if (c + 1 <= 11) convA(c + 1, av);
        if (c + 2 <= 11) ldgA(c + 2, av);

        uint32_t baseAH = sb + OFF_AH + s * 10240 + aoff;
        uint32_t baseAL = sb + OFF_AL + s * 10240 + aoff;
        uint32_t baseBH = sb + OFF_BH + s * 20480 + boff;
#pragma unroll
        for (int ks = 0; ks < 2; ks++) {
            uint32_t ah[2][4], al[2][4];
            LDMX4(ah[0], baseAH + ks * 32);
            LDMX4(ah[1], baseAH + 1280 + ks * 32);
            LDMX4(al[0], baseAL + ks * 32);
            LDMX4(al[1], baseAL + 1280 + ks * 32);
#pragma unroll
            for (int ntp = 0; ntp < 4; ntp++) {
                uint32_t bh[4];
                LDMX4(bh, baseBH + ntp * 1280 + ks * 32);
#pragma unroll
                for (int mt = 0; mt < 2; mt++) {
                    mma_f16(d[mt][2 * ntp],     ah[mt], &bh[0]);
                    mma_f16(d[mt][2 * ntp],     al[mt], &bh[0]);
                    mma_f16(d[mt][2 * ntp + 1], ah[mt], &bh[2]);
                    mma_f16(d[mt][2 * ntp + 1], al[mt], &bh[2]);
                }
            }
        }
        __syncthreads();
        if (c + 2 <= 11) { issueB(c + 2); CP_WAIT1(); }
        else if (c + 1 <= 11) { CP_WAIT0(); }
        __syncthreads();
    }

    // ---- epilogue: K warps write logits; V warps write V ----
    if (wn < 2) {
#pragma unroll
        for (int mt = 0; mt < 2; mt++) {
#pragma unroll
            for (int hh2 = 0; hh2 < 2; hh2++) {
                int e = e0 + wm * 32 + mt * 16 + qr + hh2 * 8;
                int dsti = dst_idx[e];
                const float* q = &g_Qnodes[(size_t)dsti * DD];
                float part[4] = {0.f, 0.f, 0.f, 0.f};
#pragma unroll
                for (int nt = 0; nt < 8; nt++) {
                    int cc = wn * 64 + nt * 8 + qc;
                    float v0 = d[mt][nt][hh2 * 2 + 0] + sbk[cc];
                    float v1 = d[mt][nt][hh2 * 2 + 1] + sbk[cc + 1];
                    float2 qv = *(const float2*)&q[cc];
                    part[(nt * 8 + qc) >> 4] += v0 * qv.x + v1 * qv.y;
                }
#pragma unroll
                for (int i = 0; i < 4; i++) {
                    part[i] += __shfl_xor_sync(0xffffffffu, part[i], 1);
                    part[i] += __shfl_xor_sync(0xffffffffu, part[i], 2);
                }
                if ((lane & 3) == 0) {
#pragma unroll
                    for (int hh = 0; hh < 4; hh++) {
                        int head = wn * 4 + hh;
                        float p = part[hh];
                        float l = p > 0.f ? p : 0.2f * p;
                        g_logits[(size_t)e * NH + head] = l;
                    }
                }
            }
        }
    } else {
        int cvb = (wn - 2) * 64;
#pragma unroll
        for (int mt = 0; mt < 2; mt++) {
#pragma unroll
            for (int hh2 = 0; hh2 < 2; hh2++) {
                int e = e0 + wm * 32 + mt * 16 + qr + hh2 * 8;
#pragma unroll
                for (int nt = 0; nt < 8; nt++) {
                    int cc = cvb + nt * 8 + qc;
                    float2 o;
                    o.x = d[mt][nt][hh2 * 2 + 0] + sbv[cc];
                    o.y = d[mt][nt][hh2 * 2 + 1] + sbv[cc + 1];
                    *(float2*)&g_V[(size_t)e * DD + cc] = o;
                }
            }
        }
    }
}

// ---------------- per-node softmax + aggregation (warp per dst node, no atomics) ----------------
__global__ void __launch_bounds__(256) k_node() {
    int n = blockIdx.x * 8 + (threadIdx.x >> 5);
    int lane = threadIdx.x & 31;
    int beg = g_off[n], end = g_off[n + 1];

    float mx[NH];
#pragma unroll
    for (int hh = 0; hh < NH; hh++) mx[hh] = -1e30f;
    for (int i = beg + lane; i < end; i += 32) {
        int e = g_elist[i];
        float4 l0 = *(const float4*)&g_logits[(size_t)e * NH];
        float4 l1 = *(const float4*)&g_logits[(size_t)e * NH + 4];
        mx[0] = fmaxf(mx[0], l0.x); mx[1] = fmaxf(mx[1], l0.y);
        mx[2] = fmaxf(mx[2], l0.z); mx[3] = fmaxf(mx[3], l0.w);
        mx[4] = fmaxf(mx[4], l1.x); mx[5] = fmaxf(mx[5], l1.y);
        mx[6] = fmaxf(mx[6], l1.z); mx[7] = fmaxf(mx[7], l1.w);
    }
#pragma unroll
    for (int hh = 0; hh < NH; hh++)
#pragma unroll
        for (int off = 16; off >= 1; off >>= 1)
            mx[hh] = fmaxf(mx[hh], __shfl_xor_sync(0xffffffffu, mx[hh], off));

    float sm[NH];
#pragma unroll
    for (int hh = 0; hh < NH; hh++) sm[hh] = 0.f;
    for (int i = beg + lane; i < end; i += 32) {
        int e = g_elist[i];
        float4 l0 = *(const float4*)&g_logits[(size_t)e * NH];
        float4 l1 = *(const float4*)&g_logits[(size_t)e * NH + 4];
        sm[0] += expf(l0.x - mx[0]); sm[1] += expf(l0.y - mx[1]);
        sm[2] += expf(l0.z - mx[2]); sm[3] += expf(l0.w - mx[3]);
        sm[4] += expf(l1.x - mx[4]); sm[5] += expf(l1.y - mx[5]);
        sm[6] += expf(l1.z - mx[6]); sm[7] += expf(l1.w - mx[7]);
    }
#pragma unroll
    for (int hh = 0; hh < NH; hh++)
#pragma unroll
        for (int off = 16; off >= 1; off >>= 1)
            sm[hh] += __shfl_xor_sync(0xffffffffu, sm[hh], off);

    int head = lane >> 2;
    float mh = mx[head];
    float ish = (sm[head] > 0.f) ? 1.f / sm[head] : 0.f;
    float4 acc = make_float4(0.f, 0.f, 0.f, 0.f);
    for (int i = beg; i < end; i++) {
        int e = __ldg(&g_elist[i]);
        float att = expf(g_logits[(size_t)e * NH + head] - mh) * ish;
        float4 v = *(const float4*)&g_V[(size_t)e * DD + lane * 4];
        acc.x = fmaf(att, v.x, acc.x);
        acc.y = fmaf(att, v.y, acc.y);
        acc.z = fmaf(att, v.z, acc.z);
        acc.w = fmaf(att, v.w, acc.w);
    }
    *(float4*)&g_agg[n * DD + lane * 4] = acc;
}

// ---------------- output projection + relu + layernorm ----------------
__global__ void __launch_bounds__(256) k_gemmOut(const float* __restrict__ h,
                                                 const float* __restrict__ Wout,
                                                 const float* __restrict__ bout,
                                                 const float* __restrict__ gam,
                                                 const float* __restrict__ bet,
                                                 float* __restrict__ out) {
    __shared__ float As[32][132];
    __shared__ float Bs[32][132];
    int tid = threadIdx.x, tx = tid & 15, ty = tid >> 4;
    int m0 = blockIdx.x * 128;
    float c[8][8];
#pragma unroll
    for (int i = 0; i < 8; i++)
#pragma unroll
        for (int j = 0; j < 8; j++) c[i][j] = 0.f;

    for (int kc = 0; kc < 256; kc += 32) {
#pragma unroll
        for (int r = 0; r < 16; r++) {
            int t = tid + r * 256;
            int m = t >> 5, k = t & 31;
            int kg = kc + k;
            float v;
            if (kg < 128) v = g_agg[(m0 + m) * DD + kg];
            else v = h[(size_t)(m0 + m) * DD + (kg - 128)];
            As[k][m] = v;
            Bs[k][m] = Wout[m * 256 + kg];
        }
        __syncthreads();
#pragma unroll 8
        for (int k = 0; k < 32; k++) {
            float a[8], b[8];
            *(float4*)&a[0] = *(const float4*)&As[k][ty * 8];
            *(float4*)&a[4] = *(const float4*)&As[k][ty * 8 + 4];
            *(float4*)&b[0] = *(const float4*)&Bs[k][tx * 8];
            *(float4*)&b[4] = *(const float4*)&Bs[k][tx * 8 + 4];
#pragma unroll
            for (int i = 0; i < 8; i++)
#pragma unroll
                for (int j = 0; j < 8; j++) c[i][j] = fmaf(a[i], b[j], c[i][j]);
        }
        __syncthreads();
    }

    float bj[8], gj[8], bb[8];
#pragma unroll
    for (int j = 0; j < 8; j++) {
        int col = tx * 8 + j;
        bj[j] = bout[col];
        gj[j] = gam[col];
        bb[j] = bet[col];
    }
#pragma unroll
    for (int i = 0; i < 8; i++) {
        float x[8];
        float s = 0.f, s2 = 0.f;
#pragma unroll
        for (int j = 0; j < 8; j++) {
            x[j] = fmaxf(c[i][j] + bj[j], 0.f);
            s += x[j];
            s2 += x[j] * x[j];
        }
#pragma unroll
        for (int off = 8; off >= 1; off >>= 1) {
            s  += __shfl_xor_sync(0xffffffffu, s,  off, 16);
            s2 += __shfl_xor_sync(0xffffffffu, s2, off, 16);
        }
        float mu = s * (1.f / 128.f);
        float var = s2 * (1.f / 128.f) - mu * mu;
        float inv = rsqrtf(fmaxf(var, 0.f) + 1e-5f);
        int m = m0 + ty * 8 + i;
#pragma unroll
        for (int jg = 0; jg < 2; jg++) {
            float4 o;
            o.x = (x[jg * 4 + 0] - mu) * inv * gj[jg * 4 + 0] + bb[jg * 4 + 0];
            o.y = (x[jg * 4 + 1] - mu) * inv * gj[jg * 4 + 1] + bb[jg * 4 + 1];
            o.z = (x[jg * 4 + 2] - mu) * inv * gj[jg * 4 + 2] + bb[jg * 4 + 2];
            o.w = (x[jg * 4 + 3] - mu) * inv * gj[jg * 4 + 3] + bb[jg * 4 + 3];
            *(float4*)&out[(size_t)m * DD + tx * 8 + jg * 4] = o;
        }
    }
}

// ---------------- launch ----------------
extern "C" void kernel_launch(void* const* d_in, const int* in_sizes, int n_in,
                              void* d_out, int out_size) {
    const float* h    = (const float*)d_in[0];
    const float* f    = (const float*)d_in[1];
    const float* dt   = (const float*)d_in[2];
    const int*   dst  = (const int*)d_in[3];
    const float* freq = (const float*)d_in[4];
    const float* tb   = (const float*)d_in[5];
    const float* Wq   = (const float*)d_in[6];
    const float* bq   = (const float*)d_in[7];
    const float* Wk   = (const float*)d_in[8];
    const float* bk   = (const float*)d_in[9];
    const float* Wv   = (const float*)d_in[10];
    const float* bv   = (const float*)d_in[11];
    const float* Wout = (const float*)d_in[12];
    const float* bout = (const float*)d_in[13];
    const float* gam  = (const float*)d_in[14];
    const float* bet  = (const float*)d_in[15];
    float* out = (float*)d_out;

    cudaFuncSetAttribute(k_kv, cudaFuncAttributeMaxDynamicSharedMemorySize, KV_SMEM);

    k_wconv<<<48, 1024>>>(Wk, Wv);
    k_bqeff<<<1, 128>>>(Wq, bq, tb);
    k_zero<<<ND / 256, 256>>>();
    k_count<<<NE / 256, 256>>>(dst);
    k_scan<<<1, 1024>>>();
    k_scatter<<<NE / 256, 256>>>(dst);
    k_gemmQ<<<ND / 128, 256>>>(h, Wq);
    k_kv<<<NE / 128, 512, KV_SMEM>>>(h, f, dt, freq, tb, bk, bv, dst);
    k_node<<<ND / 8, 256>>>();
    k_gemmOut<<<ND / 128, 256>>>(h, Wout, bout, gam, bet, out);
}

// round 8
// speedup vs baseline: 5.7869x; 1.2430x over previous
#include <cuda_runtime.h>
#include <cuda_fp16.h>
#include <cstdint>

#define ND 32768
#define NE 524288
#define DD 128
#define NH 8

// ---------------- scratch (static device memory; no allocations) ----------------
__device__ float    g_Qnodes[(size_t)ND * DD];   // 16 MB
__device__ float    g_V[(size_t)NE * DD];        // 256 MB
__device__ float    g_logits[(size_t)NE * NH];   // 16 MB
__device__ float    g_agg[ND * DD];              // 16 MB
__device__ float    g_bqeff[DD];
// preconverted [Wk;Wv] fp16, chunk-tiled: [12 chunks][256 rows][16 u32]
__device__ uint32_t g_WH[12 * 256 * 16];
// CSR edge binning
__device__ int g_cnt[ND];
__device__ int g_off[ND + 1];
__device__ int g_pos[ND];
__device__ int g_elist[NE];

// ---------------- CSR build ----------------
__global__ void k_zero() {
    int i = blockIdx.x * blockDim.x + threadIdx.x;
    if (i < ND) g_cnt[i] = 0;
}
__global__ void k_count(const int* __restrict__ dst_idx) {
    int e = blockIdx.x * blockDim.x + threadIdx.x;
    if (e < NE) atomicAdd(&g_cnt[dst_idx[e]], 1);
}
__global__ void __launch_bounds__(1024) k_scan() {
    __shared__ int ps[1024];
    int t = threadIdx.x;
    int base = t * 32;
    int loc[32];
    int s = 0;
#pragma unroll
    for (int j = 0; j < 32; j++) { loc[j] = s; s += g_cnt[base + j]; }
    ps[t] = s;
    __syncthreads();
    for (int off = 1; off < 1024; off <<= 1) {
        int v = (t >= off) ? ps[t - off] : 0;
        __syncthreads();
        ps[t] += v;
        __syncthreads();
    }
    int excl = (t == 0) ? 0 : ps[t - 1];
#pragma unroll
    for (int j = 0; j < 32; j++) {
        int o = excl + loc[j];
        g_off[base + j] = o;
        g_pos[base + j] = o;
    }
    if (t == 1023) g_off[ND] = ps[1023];
}
__global__ void k_scatter(const int* __restrict__ dst_idx) {
    int e = blockIdx.x * blockDim.x + threadIdx.x;
    if (e < NE) {
        int p = atomicAdd(&g_pos[dst_idx[e]], 1);
        g_elist[p] = e;
    }
}

__global__ void k_bqeff(const float* __restrict__ Wq, const float* __restrict__ bq,
                        const float* __restrict__ tb) {
    int j = threadIdx.x;
    float s = bq[j];
    for (int t = 0; t < DD; t++) s += cosf(tb[t]) * Wq[j * 256 + 128 + t];
    g_bqeff[j] = s;
}

// ======== fp16 pack helpers ========
__device__ __forceinline__ uint32_t pack2h(float x, float y) {
    __half hx = __float2half_rn(x), hy = __float2half_rn(y);
    return (uint32_t)__half_as_ushort(hx) | ((uint32_t)__half_as_ushort(hy) << 16);
}
__device__ __forceinline__ void cstoreH(uint32_t* H, int i, float4 v) {
    *(uint2*)(H + i) = make_uint2(pack2h(v.x, v.y), pack2h(v.z, v.w));
}

// ---------------- weight preconversion: single fp16 ----------------
__global__ void k_wconv(const float* __restrict__ Wk, const float* __restrict__ Wv) {
    int i = blockIdx.x * blockDim.x + threadIdx.x;   // 49152 u32 slots
    int c = i >> 12;
    int n = (i >> 4) & 255;
    int q = i & 15;
    int k = c * 32 + q * 2;
    const float* src = (n < 128) ? &Wk[n * 384 + k] : &Wv[(n - 128) * 384 + k];
    g_WH[i] = pack2h(src[0], src[1]);
}

// ---------------- Q projection (SIMT fp32, small) ----------------
__global__ void __launch_bounds__(256) k_gemmQ(const float* __restrict__ h,
                                               const float* __restrict__ Wq) {
    __shared__ float As[32][132];
    __shared__ float Bs[32][132];
    int tid = threadIdx.x, tx = tid & 15, ty = tid >> 4;
    int m0 = blockIdx.x * 128;
    float c[8][8];
#pragma unroll
    for (int i = 0; i < 8; i++)
#pragma unroll
        for (int j = 0; j < 8; j++) c[i][j] = 0.f;

    for (int kc = 0; kc < 128; kc += 32) {
#pragma unroll
        for (int r = 0; r < 16; r++) {
            int t = tid + r * 256;
            int m = t >> 5, k = t & 31;
            As[k][m] = h[(size_t)(m0 + m) * DD + kc + k];
            Bs[k][m] = Wq[m * 256 + kc + k];
        }
        __syncthreads();
#pragma unroll 8
        for (int k = 0; k < 32; k++) {
            float a[8], b[8];
            *(float4*)&a[0] = *(const float4*)&As[k][ty * 8];
            *(float4*)&a[4] = *(const float4*)&As[k][ty * 8 + 4];
            *(float4*)&b[0] = *(const float4*)&Bs[k][tx * 8];
            *(float4*)&b[4] = *(const float4*)&Bs[k][tx * 8 + 4];
#pragma unroll
            for (int i = 0; i < 8; i++)
#pragma unroll
                for (int j = 0; j < 8; j++) c[i][j] = fmaf(a[i], b[j], c[i][j]);
        }
        __syncthreads();
    }
#pragma unroll
    for (int i = 0; i < 8; i++) {
        int m = m0 + ty * 8 + i;
#pragma unroll
        for (int jg = 0; jg < 2; jg++) {
            float4 o;
            o.x = c[i][jg * 4 + 0] + g_bqeff[tx * 8 + jg * 4 + 0];
            o.y = c[i][jg * 4 + 1] + g_bqeff[tx * 8 + jg * 4 + 1];
            o.z = c[i][jg * 4 + 2] + g_bqeff[tx * 8 + jg * 4 + 2];
            o.w = c[i][jg * 4 + 3] + g_bqeff[tx * 8 + jg * 4 + 3];
            *(float4*)&g_Qnodes[(size_t)m * DD + tx * 8 + jg * 4] = o;
        }
    }
}

// ======== mma.sync / ldmatrix / cp.async primitives ========
__device__ __forceinline__ void mma_f16(float* d, const uint32_t* a, const uint32_t* b) {
    asm volatile(
        "mma.sync.aligned.m16n8k16.row.col.f32.f16.f16.f32 "
        "{%0,%1,%2,%3},{%4,%5,%6,%7},{%8,%9},{%0,%1,%2,%3};"
        : "+f"(d[0]), "+f"(d[1]), "+f"(d[2]), "+f"(d[3])
        : "r"(a[0]), "r"(a[1]), "r"(a[2]), "r"(a[3]), "r"(b[0]), "r"(b[1]));
}
#define LDMX4(r, addr) \
    asm volatile("ldmatrix.sync.aligned.m8n8.x4.shared.b16 {%0,%1,%2,%3}, [%4];" \
        : "=r"((r)[0]), "=r"((r)[1]), "=r"((r)[2]), "=r"((r)[3]) : "r"(addr))

__device__ __forceinline__ uint32_t smem_u32(const void* p) {
    uint32_t a;
    asm("{ .reg .u64 t; cvta.to.shared.u64 t, %1; cvt.u32.u64 %0, t; }" : "=r"(a) : "l"(p));
    return a;
}
#define CP_ASYNC16(saddr, gptr) \
    asm volatile("cp.async.ca.shared.global [%0], [%1], 16;" :: "r"(saddr), "l"(gptr))
#define CP_COMMIT() asm volatile("cp.async.commit_group;" ::: "memory")
#define CP_WAIT1()  asm volatile("cp.async.wait_group 1;" ::: "memory")
#define CP_WAIT0()  asm volatile("cp.async.wait_group 0;" ::: "memory")

// ---------------- SMEM layout for k_kv (dynamic, 64000 B) ----------------
// tiles: row stride 20 u32 (80 B) -> ldmatrix conflict-free, slots 0..15 used.
#define OFF_BK    0
#define OFF_BV    512
#define OFF_DT    1024
#define OFF_FREQ  1536
#define OFF_TB    2048
#define OFF_AH    2560                        // [2 stages][128*20 u32] = 2*10240
#define OFF_BH    (OFF_AH + 20480)            // 23040: [2 stages][256*20 u32] = 2*20480
#define KV_SMEM   (OFF_BH + 40960)            // 64000

// ================= fused K+V projection (pipelined mma.sync fp16, single product) =================
__global__ void __launch_bounds__(512, 1) k_kv(const float* __restrict__ h,
                                               const float* __restrict__ f,
                                               const float* __restrict__ dt,
                                               const float* __restrict__ freq,
                                               const float* __restrict__ tb,
                                               const float* __restrict__ bk,
                                               const float* __restrict__ bv,
                                               const int* __restrict__ dst_idx) {
    extern __shared__ char smem[];
    uint32_t sb = smem_u32(smem);
    int tid = threadIdx.x, wid = tid >> 5, lane = tid & 31;
    int e0 = blockIdx.x * 128;

    float* sbk   = (float*)(smem + OFF_BK);
    float* sbv   = (float*)(smem + OFF_BV);
    float* dts   = (float*)(smem + OFF_DT);
    float* freqs = (float*)(smem + OFF_FREQ);
    float* tbs   = (float*)(smem + OFF_TB);
    if (tid < 128) {
        sbk[tid] = bk[tid];
        sbv[tid] = bv[tid];
        dts[tid] = dt[e0 + tid];
        freqs[tid] = freq[tid];
        tbs[tid] = tb[tid];
    }

    auto issueB = [&](int g) {
        int s = g & 1;
#pragma unroll
        for (int r = 0; r < 2; r++) {
            int idx = tid + r * 512;
            int n = idx >> 2, q4 = (idx & 3) * 4;
            CP_ASYNC16(sb + OFF_BH + s * 20480 + (n * 20 + q4) * 4,
                       &g_WH[(g * 256 + n) * 16 + q4]);
        }
        CP_COMMIT();
    };

    auto ldgA = [&](int g, float4* av) {
        if (g < 8) {
            const float* base = (g < 4) ? h + (size_t)(ND + e0) * DD + g * 32
                                        : f + (size_t)e0 * DD + (g - 4) * 32;
#pragma unroll
            for (int r = 0; r < 2; r++) {
                int idx = tid + r * 512;
                int m = idx >> 3, kq = (idx & 7) * 4;
                av[r] = *(const float4*)(base + (size_t)m * DD + kq);
            }
        }
    };
    auto convA = [&](int g, const float4* av) {
        int s = g & 1;
        uint32_t* AH = (uint32_t*)(smem + OFF_AH + s * 10240);
#pragma unroll
        for (int r = 0; r < 2; r++) {
            int idx = tid + r * 512;
            int m = idx >> 3, kq = (idx & 7) * 4;
            float4 v;
            if (g < 8) v = av[r];
            else {
                int ko = (g - 8) * 32 + kq;
                float d = dts[m];
                v.x = __cosf(fmaf(d, freqs[ko + 0], tbs[ko + 0]));
                v.y = __cosf(fmaf(d, freqs[ko + 1], tbs[ko + 1]));
                v.z = __cosf(fmaf(d, freqs[ko + 2], tbs[ko + 2]));
                v.w = __cosf(fmaf(d, freqs[ko + 3], tbs[ko + 3]));
            }
            cstoreH(AH, m * 20 + (kq >> 1), v);
        }
    };

    int wm = wid & 3, wn = wid >> 2;
    int qr = lane >> 2, qc = (lane & 3) * 2;
    float d[2][8][4];
#pragma unroll
    for (int mt = 0; mt < 2; mt++)
#pragma unroll
        for (int nt = 0; nt < 8; nt++)
#pragma unroll
            for (int j = 0; j < 4; j++) d[mt][nt][j] = 0.f;

    uint32_t aoff = (uint32_t)(wm * 32 + (lane & 7) + ((lane >> 3) & 1) * 8) * 80
                  + ((lane >> 4) & 1) * 16;
    uint32_t boff = (uint32_t)(wn * 64 + (lane & 7) + ((lane >> 4) & 1) * 8) * 80
                  + ((lane >> 3) & 1) * 16;

    float4 av[2];
    issueB(0);
    issueB(1);
    ldgA(0, av);
    convA(0, av);
    ldgA(1, av);
    CP_WAIT1();
    __syncthreads();

    for (int c = 0; c < 12; c++) {
        int s = c & 1;
        if (c + 1 <= 11) convA(c + 1, av);
        if (c + 2 <= 11) ldgA(c + 2, av);

        uint32_t baseAH = sb + OFF_AH + s * 10240 + aoff;
        uint32_t baseBH = sb + OFF_BH + s * 20480 + boff;
#pragma unroll
        for (int ks = 0; ks < 2; ks++) {
            uint32_t ah[2][4];
            LDMX4(ah[0], baseAH + ks * 32);
            LDMX4(ah[1], baseAH + 1280 + ks * 32);
#pragma unroll
            for (int ntp = 0; ntp < 4; ntp++) {
                uint32_t bh[4];
                LDMX4(bh, baseBH + ntp * 1280 + ks * 32);
#pragma unroll
                for (int mt = 0; mt < 2; mt++) {
                    mma_f16(d[mt][2 * ntp],     ah[mt], &bh[0]);
                    mma_f16(d[mt][2 * ntp + 1], ah[mt], &bh[2]);
                }
            }
        }
        __syncthreads();
        if (c + 2 <= 11) { issueB(c + 2); CP_WAIT1(); }
        else if (c + 1 <= 11) { CP_WAIT0(); }
        __syncthreads();
    }

    // ---- epilogue: K warps write logits; V warps write V ----
    if (wn < 2) {
#pragma unroll
        for (int mt = 0; mt < 2; mt++) {
#pragma unroll
            for (int hh2 = 0; hh2 < 2; hh2++) {
                int e = e0 + wm * 32 + mt * 16 + qr + hh2 * 8;
                int dsti = dst_idx[e];
                const float* q = &g_Qnodes[(size_t)dsti * DD];
                float part[4] = {0.f, 0.f, 0.f, 0.f};
#pragma unroll
                for (int nt = 0; nt < 8; nt++) {
                    int cc = wn * 64 + nt * 8 + qc;
                    float v0 = d[mt][nt][hh2 * 2 + 0] + sbk[cc];
                    float v1 = d[mt][nt][hh2 * 2 + 1] + sbk[cc + 1];
                    float2 qv = *(const float2*)&q[cc];
                    part[(nt * 8 + qc) >> 4] += v0 * qv.x + v1 * qv.y;
                }
#pragma unroll
                for (int i = 0; i < 4; i++) {
                    part[i] += __shfl_xor_sync(0xffffffffu, part[i], 1);
                    part[i] += __shfl_xor_sync(0xffffffffu, part[i], 2);
                }
                if ((lane & 3) == 0) {
#pragma unroll
                    for (int hh = 0; hh < 4; hh++) {
                        int head = wn * 4 + hh;
                        float p = part[hh];
                        float l = p > 0.f ? p : 0.2f * p;
                        g_logits[(size_t)e * NH + head] = l;
                    }
                }
            }
        }
    } else {
        int cvb = (wn - 2) * 64;
#pragma unroll
        for (int mt = 0; mt < 2; mt++) {
#pragma unroll
            for (int hh2 = 0; hh2 < 2; hh2++) {
                int e = e0 + wm * 32 + mt * 16 + qr + hh2 * 8;
#pragma unroll
                for (int nt = 0; nt < 8; nt++) {
                    int cc = cvb + nt * 8 + qc;
                    float2 o;
                    o.x = d[mt][nt][hh2 * 2 + 0] + sbv[cc];
                    o.y = d[mt][nt][hh2 * 2 + 1] + sbv[cc + 1];
                    *(float2*)&g_V[(size_t)e * DD + cc] = o;
                }
            }
        }
    }
}

// ---------------- per-node softmax + aggregation (warp per dst node, no atomics) ----------------
__global__ void __launch_bounds__(256) k_node() {
    int n = blockIdx.x * 8 + (threadIdx.x >> 5);
    int lane = threadIdx.x & 31;
    int beg = g_off[n], end = g_off[n + 1];

    float mx[NH];
#pragma unroll
    for (int hh = 0; hh < NH; hh++) mx[hh] = -1e30f;
    for (int i = beg + lane; i < end; i += 32) {
        int e = g_elist[i];
        float4 l0 = *(const float4*)&g_logits[(size_t)e * NH];
        float4 l1 = *(const float4*)&g_logits[(size_t)e * NH + 4];
        mx[0] = fmaxf(mx[0], l0.x); mx[1] = fmaxf(mx[1], l0.y);
        mx[2] = fmaxf(mx[2], l0.z); mx[3] = fmaxf(mx[3], l0.w);
        mx[4] = fmaxf(mx[4], l1.x); mx[5] = fmaxf(mx[5], l1.y);
        mx[6] = fmaxf(mx[6], l1.z); mx[7] = fmaxf(mx[7], l1.w);
    }
#pragma unroll
    for (int hh = 0; hh < NH; hh++)
#pragma unroll
        for (int off = 16; off >= 1; off >>= 1)
            mx[hh] = fmaxf(mx[hh], __shfl_xor_sync(0xffffffffu, mx[hh], off));

    float sm[NH];
#pragma unroll
    for (int hh = 0; hh < NH; hh++) sm[hh] = 0.f;
    for (int i = beg + lane; i < end; i += 32) {
        int e = g_elist[i];
        float4 l0 = *(const float4*)&g_logits[(size_t)e * NH];
        float4 l1 = *(const float4*)&g_logits[(size_t)e * NH + 4];
        sm[0] += expf(l0.x - mx[0]); sm[1] += expf(l0.y - mx[1]);
        sm[2] += expf(l0.z - mx[2]); sm[3] += expf(l0.w - mx[3]);
        sm[4] += expf(l1.x - mx[4]); sm[5] += expf(l1.y - mx[5]);
        sm[6] += expf(l1.z - mx[6]); sm[7] += expf(l1.w - mx[7]);
    }
#pragma unroll
    for (int hh = 0; hh < NH; hh++)
#pragma unroll
        for (int off = 16; off >= 1; off >>= 1)
            sm[hh] += __shfl_xor_sync(0xffffffffu, sm[hh], off);

    int head = lane >> 2;
    float mh = mx[head];
    float ish = (sm[head] > 0.f) ? 1.f / sm[head] : 0.f;
    float4 acc = make_float4(0.f, 0.f, 0.f, 0.f);
    for (int i = beg; i < end; i++) {
        int e = __ldg(&g_elist[i]);
        float att = expf(g_logits[(size_t)e * NH + head] - mh) * ish;
        float4 v = *(const float4*)&g_V[(size_t)e * DD + lane * 4];
        acc.x = fmaf(att, v.x, acc.x);
        acc.y = fmaf(att, v.y, acc.y);
        acc.z = fmaf(att, v.z, acc.z);
        acc.w = fmaf(att, v.w, acc.w);
    }
    *(float4*)&g_agg[n * DD + lane * 4] = acc;
}

// ---------------- output projection + relu + layernorm ----------------
__global__ void __launch_bounds__(256) k_gemmOut(const float* __restrict__ h,
                                                 const float* __restrict__ Wout,
                                                 const float* __restrict__ bout,
                                                 const float* __restrict__ gam,
                                                 const float* __restrict__ bet,
                                                 float* __restrict__ out) {
    __shared__ float As[32][132];
    __shared__ float Bs[32][132];
    int tid = threadIdx.x, tx = tid & 15, ty = tid >> 4;
    int m0 = blockIdx.x * 128;
    float c[8][8];
#pragma unroll
    for (int i = 0; i < 8; i++)
#pragma unroll
        for (int j = 0; j < 8; j++) c[i][j] = 0.f;

    for (int kc = 0; kc < 256; kc += 32) {
#pragma unroll
        for (int r = 0; r < 16; r++) {
            int t = tid + r * 256;
            int m = t >> 5, k = t & 31;
            int kg = kc + k;
            float v;
            if (kg < 128) v = g_agg[(m0 + m) * DD + kg];
            else v = h[(size_t)(m0 + m) * DD + (kg - 128)];
            As[k][m] = v;
            Bs[k][m] = Wout[m * 256 + kg];
        }
        __syncthreads();
#pragma unroll 8
        for (int k = 0; k < 32; k++) {
            float a[8], b[8];
            *(float4*)&a[0] = *(const float4*)&As[k][ty * 8];
            *(float4*)&a[4] = *(const float4*)&As[k][ty * 8 + 4];
            *(float4*)&b[0] = *(const float4*)&Bs[k][tx * 8];
            *(float4*)&b[4] = *(const float4*)&Bs[k][tx * 8 + 4];
#pragma unroll
            for (int i = 0; i < 8; i++)
#pragma unroll
                for (int j = 0; j < 8; j++) c[i][j] = fmaf(a[i], b[j], c[i][j]);
        }
        __syncthreads();
    }

    float bj[8], gj[8], bb[8];
#pragma unroll
    for (int j = 0; j < 8; j++) {
        int col = tx * 8 + j;
        bj[j] = bout[col];
        gj[j] = gam[col];
        bb[j] = bet[col];
    }
#pragma unroll
    for (int i = 0; i < 8; i++) {
        float x[8];
        float s = 0.f, s2 = 0.f;
#pragma unroll
        for (int j = 0; j < 8; j++) {
            x[j] = fmaxf(c[i][j] + bj[j], 0.f);
            s += x[j];
            s2 += x[j] * x[j];
        }
#pragma unroll
        for (int off = 8; off >= 1; off >>= 1) {
            s  += __shfl_xor_sync(0xffffffffu, s,  off, 16);
            s2 += __shfl_xor_sync(0xffffffffu, s2, off, 16);
        }
        float mu = s * (1.f / 128.f);
        float var = s2 * (1.f / 128.f) - mu * mu;
        float inv = rsqrtf(fmaxf(var, 0.f) + 1e-5f);
        int m = m0 + ty * 8 + i;
#pragma unroll
        for (int jg = 0; jg < 2; jg++) {
            float4 o;
            o.x = (x[jg * 4 + 0] - mu) * inv * gj[jg * 4 + 0] + bb[jg * 4 + 0];
            o.y = (x[jg * 4 + 1] - mu) * inv * gj[jg * 4 + 1] + bb[jg * 4 + 1];
            o.z = (x[jg * 4 + 2] - mu) * inv * gj[jg * 4 + 2] + bb[jg * 4 + 2];
            o.w = (x[jg * 4 + 3] - mu) * inv * gj[jg * 4 + 3] + bb[jg * 4 + 3];
            *(float4*)&out[(size_t)m * DD + tx * 8 + jg * 4] = o;
        }
    }
}

// ---------------- launch ----------------
extern "C" void kernel_launch(void* const* d_in, const int* in_sizes, int n_in,
                              void* d_out, int out_size) {
    const float* h    = (const float*)d_in[0];
    const float* f    = (const float*)d_in[1];
    const float* dt   = (const float*)d_in[2];
    const int*   dst  = (const int*)d_in[3];
    const float* freq = (const float*)d_in[4];
    const float* tb   = (const float*)d_in[5];
    const float* Wq   = (const float*)d_in[6];
    const float* bq   = (const float*)d_in[7];
    const float* Wk   = (const float*)d_in[8];
    const float* bk   = (const float*)d_in[9];
    const float* Wv   = (const float*)d_in[10];
    const float* bv   = (const float*)d_in[11];
    const float* Wout = (const float*)d_in[12];
    const float* bout = (const float*)d_in[13];
    const float* gam  = (const float*)d_in[14];
    const float* bet  = (const float*)d_in[15];
    float* out = (float*)d_out;

    cudaFuncSetAttribute(k_kv, cudaFuncAttributeMaxDynamicSharedMemorySize, KV_SMEM);

    k_wconv<<<48, 1024>>>(Wk, Wv);
    k_bqeff<<<1, 128>>>(Wq, bq, tb);
    k_zero<<<ND / 256, 256>>>();
    k_count<<<NE / 256, 256>>>(dst);
    k_scan<<<1, 1024>>>();
    k_scatter<<<NE / 256, 256>>>(dst);
    k_gemmQ<<<ND / 128, 256>>>(h, Wq);
    k_kv<<<NE / 128, 512, KV_SMEM>>>(h, f, dt, freq, tb, bk, bv, dst);
    k_node<<<ND / 8, 256>>>();
    k_gemmOut<<<ND / 128, 256>>>(h, Wout, bout, gam, bet, out);
}

// round 9
// speedup vs baseline: 5.9235x; 1.0236x over previous
#include <cuda_runtime.h>
#include <cuda_fp16.h>
#include <cstdint>

#define ND 32768
#define NE 524288
#define DD 128
#define NH 8

// ---------------- scratch (static device memory; no allocations) ----------------
__device__ float    g_Qnodes[(size_t)ND * DD];   // 16 MB
__device__ __half   g_Vh[(size_t)NE * DD];       // 128 MB (fp16 V)
__device__ float    g_logits[(size_t)NE * NH];   // 16 MB
__device__ float    g_agg[ND * DD];              // 16 MB
__device__ float    g_bqeff[DD];
// preconverted [Wk;Wv] fp16, chunk-tiled: [12 chunks][256 rows][16 u32]
__device__ uint32_t g_WH[12 * 256 * 16];
// CSR edge binning
__device__ int g_cnt[ND];
__device__ int g_off[ND + 1];
__device__ int g_pos[ND];
__device__ int g_elist[NE];

// ---------------- CSR build ----------------
__global__ void k_zero() {
    int i = blockIdx.x * blockDim.x + threadIdx.x;
    if (i < ND) g_cnt[i] = 0;
}
__global__ void k_count(const int* __restrict__ dst_idx) {
    int e = blockIdx.x * blockDim.x + threadIdx.x;
    if (e < NE) atomicAdd(&g_cnt[dst_idx[e]], 1);
}
__global__ void __launch_bounds__(1024) k_scan() {
    __shared__ int ps[1024];
    int t = threadIdx.x;
    int base = t * 32;
    int loc[32];
    int s = 0;
#pragma unroll
    for (int j = 0; j < 32; j++) { loc[j] = s; s += g_cnt[base + j]; }
    ps[t] = s;
    __syncthreads();
    for (int off = 1; off < 1024; off <<= 1) {
        int v = (t >= off) ? ps[t - off] : 0;
        __syncthreads();
        ps[t] += v;
        __syncthreads();
    }
    int excl = (t == 0) ? 0 : ps[t - 1];
#pragma unroll
    for (int j = 0; j < 32; j++) {
        int o = excl + loc[j];
        g_off[base + j] = o;
        g_pos[base + j] = o;
    }
    if (t == 1023) g_off[ND] = ps[1023];
}
__global__ void k_scatter(const int* __restrict__ dst_idx) {
    int e = blockIdx.x * blockDim.x + threadIdx.x;
    if (e < NE) {
        int p = atomicAdd(&g_pos[dst_idx[e]], 1);
        g_elist[p] = e;
    }
}

__global__ void k_bqeff(const float* __restrict__ Wq, const float* __restrict__ bq,
                        const float* __restrict__ tb) {
    int j = threadIdx.x;
    float s = bq[j];
    for (int t = 0; t < DD; t++) s += cosf(tb[t]) * Wq[j * 256 + 128 + t];
    g_bqeff[j] = s;
}

// ======== fp16 pack helpers ========
__device__ __forceinline__ uint32_t pack2h(float x, float y) {
    __half hx = __float2half_rn(x), hy = __float2half_rn(y);
    return (uint32_t)__half_as_ushort(hx) | ((uint32_t)__half_as_ushort(hy) << 16);
}
__device__ __forceinline__ void cstoreH(uint32_t* H, int i, float4 v) {
    *(uint2*)(H + i) = make_uint2(pack2h(v.x, v.y), pack2h(v.z, v.w));
}

// ---------------- weight preconversion: single fp16 ----------------
__global__ void k_wconv(const float* __restrict__ Wk, const float* __restrict__ Wv) {
    int i = blockIdx.x * blockDim.x + threadIdx.x;   // 49152 u32 slots
    int c = i >> 12;
    int n = (i >> 4) & 255;
    int q = i & 15;
    int k = c * 32 + q * 2;
    const float* src = (n < 128) ? &Wk[n * 384 + k] : &Wv[(n - 128) * 384 + k];
    g_WH[i] = pack2h(src[0], src[1]);
}

// ---------------- Q projection (SIMT fp32, small) ----------------
__global__ void __launch_bounds__(256) k_gemmQ(const float* __restrict__ h,
                                               const float* __restrict__ Wq) {
    __shared__ float As[32][132];
    __shared__ float Bs[32][132];
    int tid = threadIdx.x, tx = tid & 15, ty = tid >> 4;
    int m0 = blockIdx.x * 128;
    float c[8][8];
#pragma unroll
    for (int i = 0; i < 8; i++)
#pragma unroll
        for (int j = 0; j < 8; j++) c[i][j] = 0.f;

    for (int kc = 0; kc < 128; kc += 32) {
#pragma unroll
        for (int r = 0; r < 16; r++) {
            int t = tid + r * 256;
            int m = t >> 5, k = t & 31;
            As[k][m] = h[(size_t)(m0 + m) * DD + kc + k];
            Bs[k][m] = Wq[m * 256 + kc + k];
        }
        __syncthreads();
#pragma unroll 8
        for (int k = 0; k < 32; k++) {
            float a[8], b[8];
            *(float4*)&a[0] = *(const float4*)&As[k][ty * 8];
            *(float4*)&a[4] = *(const float4*)&As[k][ty * 8 + 4];
            *(float4*)&b[0] = *(const float4*)&Bs[k][tx * 8];
            *(float4*)&b[4] = *(const float4*)&Bs[k][tx * 8 + 4];
#pragma unroll
            for (int i = 0; i < 8; i++)
#pragma unroll
                for (int j = 0; j < 8; j++) c[i][j] = fmaf(a[i], b[j], c[i][j]);
        }
        __syncthreads();
    }
#pragma unroll
    for (int i = 0; i < 8; i++) {
        int m = m0 + ty * 8 + i;
#pragma unroll
        for (int jg = 0; jg < 2; jg++) {
            float4 o;
            o.x = c[i][jg * 4 + 0] + g_bqeff[tx * 8 + jg * 4 + 0];
            o.y = c[i][jg * 4 + 1] + g_bqeff[tx * 8 + jg * 4 + 1];
            o.z = c[i][jg * 4 + 2] + g_bqeff[tx * 8 + jg * 4 + 2];
            o.w = c[i][jg * 4 + 3] + g_bqeff[tx * 8 + jg * 4 + 3];
            *(float4*)&g_Qnodes[(size_t)m * DD + tx * 8 + jg * 4] = o;
        }
    }
}

// ======== mma.sync / ldmatrix / cp.async primitives ========
__device__ __forceinline__ void mma_f16(float* d, const uint32_t* a, const uint32_t* b) {
    asm volatile(
        "mma.sync.aligned.m16n8k16.row.col.f32.f16.f16.f32 "
        "{%0,%1,%2,%3},{%4,%5,%6,%7},{%8,%9},{%0,%1,%2,%3};"
        : "+f"(d[0]), "+f"(d[1]), "+f"(d[2]), "+f"(d[3])
        : "r"(a[0]), "r"(a[1]), "r"(a[2]), "r"(a[3]), "r"(b[0]), "r"(b[1]));
}
#define LDMX4(r, addr) \
    asm volatile("ldmatrix.sync.aligned.m8n8.x4.shared.b16 {%0,%1,%2,%3}, [%4];" \
        : "=r"((r)[0]), "=r"((r)[1]), "=r"((r)[2]), "=r"((r)[3]) : "r"(addr))

__device__ __forceinline__ uint32_t smem_u32(const void* p) {
    uint32_t a;
    asm("{ .reg .u64 t; cvta.to.shared.u64 t, %1; cvt.u32.u64 %0, t; }" : "=r"(a) : "l"(p));
    return a;
}
#define CP_ASYNC16(saddr, gptr) \
    asm volatile("cp.async.ca.shared.global [%0], [%1], 16;" :: "r"(saddr), "l"(gptr))
#define CP_COMMIT() asm volatile("cp.async.commit_group;" ::: "memory")
#define CP_WAIT1()  asm volatile("cp.async.wait_group 1;" ::: "memory")
#define CP_WAIT0()  asm volatile("cp.async.wait_group 0;" ::: "memory")

// ---------------- SMEM layout for k_kv (dynamic, 64000 B) ----------------
#define OFF_BK    0
#define OFF_BV    512
#define OFF_DT    1024
#define OFF_FREQ  1536
#define OFF_TB    2048
#define OFF_AH    2560                        // [2 stages][128*20 u32] = 2*10240
#define OFF_BH    (OFF_AH + 20480)            // 23040: [2 stages][256*20 u32] = 2*20480
#define KV_SMEM   (OFF_BH + 40960)            // 64000

// ================= fused K+V projection (pipelined mma.sync fp16, single product) =================
__global__ void __launch_bounds__(512, 1) k_kv(const float* __restrict__ h,
                                               const float* __restrict__ f,
                                               const float* __restrict__ dt,
                                               const float* __restrict__ freq,
                                               const float* __restrict__ tb,
                                               const float* __restrict__ bk,
                                               const float* __restrict__ bv,
                                               const int* __restrict__ dst_idx) {
    extern __shared__ char smem[];
    uint32_t sb = smem_u32(smem);
    int tid = threadIdx.x, wid = tid >> 5, lane = tid & 31;
    int e0 = blockIdx.x * 128;

    float* sbk   = (float*)(smem + OFF_BK);
    float* sbv   = (float*)(smem + OFF_BV);
    float* dts   = (float*)(smem + OFF_DT);
    float* freqs = (float*)(smem + OFF_FREQ);
    float* tbs   = (float*)(smem + OFF_TB);
    if (tid < 128) {
        sbk[tid] = bk[tid];
        sbv[tid] = bv[tid];
        dts[tid] = dt[e0 + tid];
        freqs[tid] = freq[tid];
        tbs[tid] = tb[tid];
    }

    auto issueB = [&](int g) {
        int s = g & 1;
#pragma unroll
        for (int r = 0; r < 2; r++) {
            int idx = tid + r * 512;
            int n = idx >> 2, q4 = (idx & 3) * 4;
            CP_ASYNC16(sb + OFF_BH + s * 20480 + (n * 20 + q4) * 4,
                       &g_WH[(g * 256 + n) * 16 + q4]);
        }
        CP_COMMIT();
    };

    auto ldgA = [&](int g, float4* av) {
        if (g < 8) {
            const float* base = (g < 4) ? h + (size_t)(ND + e0) * DD + g * 32
                                        : f + (size_t)e0 * DD + (g - 4) * 32;
#pragma unroll
            for (int r = 0; r < 2; r++) {
                int idx = tid + r * 512;
                int m = idx >> 3, kq = (idx & 7) * 4;
                av[r] = *(const float4*)(base + (size_t)m * DD + kq);
            }
        }
    };
    auto convA = [&](int g, const float4* av) {
        int s = g & 1;
        uint32_t* AH = (uint32_t*)(smem + OFF_AH + s * 10240);
#pragma unroll
        for (int r = 0; r < 2; r++) {
            int idx = tid + r * 512;
            int m = idx >> 3, kq = (idx & 7) * 4;
            float4 v;
            if (g < 8) v = av[r];
            else {
                int ko = (g - 8) * 32 + kq;
                float d = dts[m];
                v.x = __cosf(fmaf(d, freqs[ko + 0], tbs[ko + 0]));
                v.y = __cosf(fmaf(d, freqs[ko + 1], tbs[ko + 1]));
                v.z = __cosf(fmaf(d, freqs[ko + 2], tbs[ko + 2]));
                v.w = __cosf(fmaf(d, freqs[ko + 3], tbs[ko + 3]));
            }
            cstoreH(AH, m * 20 + (kq >> 1), v);
        }
    };

    int wm = wid & 3, wn = wid >> 2;
    int qr = lane >> 2, qc = (lane & 3) * 2;
    float d[2][8][4];
#pragma unroll
    for (int mt = 0; mt < 2; mt++)
#pragma unroll
        for (int nt = 0; nt < 8; nt++)
#pragma unroll
            for (int j = 0; j < 4; j++) d[mt][nt][j] = 0.f;

    uint32_t aoff = (uint32_t)(wm * 32 + (lane & 7) + ((lane >> 3) & 1) * 8) * 80
                  + ((lane >> 4) & 1) * 16;
    uint32_t boff = (uint32_t)(wn * 64 + (lane & 7) + ((lane >> 4) & 1) * 8) * 80
                  + ((lane >> 3) & 1) * 16;

    float4 av[2];
    issueB(0);
    issueB(1);
    ldgA(0, av);
    convA(0, av);
    ldgA(1, av);
    CP_WAIT1();
    __syncthreads();

    for (int c = 0; c < 12; c++) {
        int s = c & 1;
        if (c + 1 <= 11) convA(c + 1, av);
        if (c + 2 <= 11) ldgA(c + 2, av);

        uint32_t baseAH = sb + OFF_AH + s * 10240 + aoff;
        uint32_t baseBH = sb + OFF_BH + s * 20480 + boff;
#pragma unroll
        for (int ks = 0; ks < 2; ks++) {
            uint32_t ah[2][4];
            LDMX4(ah[0], baseAH + ks * 32);
            LDMX4(ah[1], baseAH + 1280 + ks * 32);
#pragma unroll
            for (int ntp = 0; ntp < 4; ntp++) {
                uint32_t bh[4];
                LDMX4(bh, baseBH + ntp * 1280 + ks * 32);
#pragma unroll
                for (int mt = 0; mt < 2; mt++) {
                    mma_f16(d[mt][2 * ntp],     ah[mt], &bh[0]);
                    mma_f16(d[mt][2 * ntp + 1], ah[mt], &bh[2]);
                }
            }
        }
        __syncthreads();
        if (c + 2 <= 11) { issueB(c + 2); CP_WAIT1(); }
        else if (c + 1 <= 11) { CP_WAIT0(); }
        __syncthreads();
    }

    // ---- epilogue: K warps write logits; V warps write V (fp16) ----
    if (wn < 2) {
#pragma unroll
        for (int mt = 0; mt < 2; mt++) {
#pragma unroll
            for (int hh2 = 0; hh2 < 2; hh2++) {
                int e = e0 + wm * 32 + mt * 16 + qr + hh2 * 8;
                int dsti = dst_idx[e];
                const float* q = &g_Qnodes[(size_t)dsti * DD];
                float part[4] = {0.f, 0.f, 0.f, 0.f};
#pragma unroll
                for (int nt = 0; nt < 8; nt++) {
                    int cc = wn * 64 + nt * 8 + qc;
                    float v0 = d[mt][nt][hh2 * 2 + 0] + sbk[cc];
                    float v1 = d[mt][nt][hh2 * 2 + 1] + sbk[cc + 1];
                    float2 qv = *(const float2*)&q[cc];
                    part[(nt * 8 + qc) >> 4] += v0 * qv.x + v1 * qv.y;
                }
#pragma unroll
                for (int i = 0; i < 4; i++) {
                    part[i] += __shfl_xor_sync(0xffffffffu, part[i], 1);
                    part[i] += __shfl_xor_sync(0xffffffffu, part[i], 2);
                }
                if ((lane & 3) == 0) {
#pragma unroll
                    for (int hh = 0; hh < 4; hh++) {
                        int head = wn * 4 + hh;
                        float p = part[hh];
                        float l = p > 0.f ? p : 0.2f * p;
                        g_logits[(size_t)e * NH + head] = l;
                    }
                }
            }
        }
    } else {
        int cvb = (wn - 2) * 64;
#pragma unroll
        for (int mt = 0; mt < 2; mt++) {
#pragma unroll
            for (int hh2 = 0; hh2 < 2; hh2++) {
                int e = e0 + wm * 32 + mt * 16 + qr + hh2 * 8;
#pragma unroll
                for (int nt = 0; nt < 8; nt++) {
                    int cc = cvb + nt * 8 + qc;
                    float v0 = d[mt][nt][hh2 * 2 + 0] + sbv[cc];
                    float v1 = d[mt][nt][hh2 * 2 + 1] + sbv[cc + 1];
                    *(uint32_t*)&g_Vh[(size_t)e * DD + cc] = pack2h(v0, v1);
                }
            }
        }
    }
}

// ---------------- per-node softmax + aggregation (warp per dst node, no atomics) ----------------
__global__ void __launch_bounds__(256) k_node() {
    int n = blockIdx.x * 8 + (threadIdx.x >> 5);
    int lane = threadIdx.x & 31;
    int beg = g_off[n], end = g_off[n + 1];

    float mx[NH];
#pragma unroll
    for (int hh = 0; hh < NH; hh++) mx[hh] = -1e30f;
    for (int i = beg + lane; i < end; i += 32) {
        int e = g_elist[i];
        float4 l0 = *(const float4*)&g_logits[(size_t)e * NH];
        float4 l1 = *(const float4*)&g_logits[(size_t)e * NH + 4];
        mx[0] = fmaxf(mx[0], l0.x); mx[1] = fmaxf(mx[1], l0.y);
        mx[2] = fmaxf(mx[2], l0.z); mx[3] = fmaxf(mx[3], l0.w);
        mx[4] = fmaxf(mx[4], l1.x); mx[5] = fmaxf(mx[5], l1.y);
        mx[6] = fmaxf(mx[6], l1.z); mx[7] = fmaxf(mx[7], l1.w);
    }
#pragma unroll
    for (int hh = 0; hh < NH; hh++)
#pragma unroll
        for (int off = 16; off >= 1; off >>= 1)
            mx[hh] = fmaxf(mx[hh], __shfl_xor_sync(0xffffffffu, mx[hh], off));

    float sm[NH];
#pragma unroll
    for (int hh = 0; hh < NH; hh++) sm[hh] = 0.f;
    for (int i = beg + lane; i < end; i += 32) {
        int e = g_elist[i];
        float4 l0 = *(const float4*)&g_logits[(size_t)e * NH];
        float4 l1 = *(const float4*)&g_logits[(size_t)e * NH + 4];
        sm[0] += expf(l0.x - mx[0]); sm[1] += expf(l0.y - mx[1]);
        sm[2] += expf(l0.z - mx[2]); sm[3] += expf(l0.w - mx[3]);
        sm[4] += expf(l1.x - mx[4]); sm[5] += expf(l1.y - mx[5]);
        sm[6] += expf(l1.z - mx[6]); sm[7] += expf(l1.w - mx[7]);
    }
#pragma unroll
    for (int hh = 0; hh < NH; hh++)
#pragma unroll
        for (int off = 16; off >= 1; off >>= 1)
            sm[hh] += __shfl_xor_sync(0xffffffffu, sm[hh], off);

    int head = lane >> 2;
    float mh = mx[head];
    float ish = (sm[head] > 0.f) ? 1.f / sm[head] : 0.f;
    float4 acc = make_float4(0.f, 0.f, 0.f, 0.f);
    for (int i = beg; i < end; i++) {
        int e = __ldg(&g_elist[i]);
        float att = expf(g_logits[(size_t)e * NH + head] - mh) * ish;
        uint2 vp = *(const uint2*)&g_Vh[(size_t)e * DD + lane * 4];
        float2 v01 = __half22float2(*(const __half2*)&vp.x);
        float2 v23 = __half22float2(*(const __half2*)&vp.y);
        acc.x = fmaf(att, v01.x, acc.x);
        acc.y = fmaf(att, v01.y, acc.y);
        acc.z = fmaf(att, v23.x, acc.z);
        acc.w = fmaf(att, v23.y, acc.w);
    }
    *(float4*)&g_agg[n * DD + lane * 4] = acc;
}

// ---------------- output projection + relu + layernorm ----------------
__global__ void __launch_bounds__(256) k_gemmOut(const float* __restrict__ h,
                                                 const float* __restrict__ Wout,
                                                 const float* __restrict__ bout,
                                                 const float* __restrict__ gam,
                                                 const float* __restrict__ bet,
                                                 float* __restrict__ out) {
    __shared__ float As[32][132];
    __shared__ float Bs[32][132];
    int tid = threadIdx.x, tx = tid & 15, ty = tid >> 4;
    int m0 = blockIdx.x * 128;
    float c[8][8];
#pragma unroll
    for (int i = 0; i < 8; i++)
#pragma unroll
        for (int j = 0; j < 8; j++) c[i][j] = 0.f;

    for (int kc = 0; kc < 256; kc += 32) {
#pragma unroll
        for (int r = 0; r < 16; r++) {
            int t = tid + r * 256;
            int m = t >> 5, k = t & 31;
            int kg = kc + k;
            float v;
            if (kg < 128) v = g_agg[(m0 + m) * DD + kg];
            else v = h[(size_t)(m0 + m) * DD + (kg - 128)];
            As[k][m] = v;
            Bs[k][m] = Wout[m * 256 + kg];
        }
        __syncthreads();
#pragma unroll 8
        for (int k = 0; k < 32; k++) {
            float a[8], b[8];
            *(float4*)&a[0] = *(const float4*)&As[k][ty * 8];
            *(float4*)&a[4] = *(const float4*)&As[k][ty * 8 + 4];
            *(float4*)&b[0] = *(const float4*)&Bs[k][tx * 8];
            *(float4*)&b[4] = *(const float4*)&Bs[k][tx * 8 + 4];
#pragma unroll
            for (int i = 0; i < 8; i++)
#pragma unroll
                for (int j = 0; j < 8; j++) c[i][j] = fmaf(a[i], b[j], c[i][j]);
        }
        __syncthreads();
    }

    float bj[8], gj[8], bb[8];
#pragma unroll
    for (int j = 0; j < 8; j++) {
        int col = tx * 8 + j;
        bj[j] = bout[col];
        gj[j] = gam[col];
        bb[j] = bet[col];
    }
#pragma unroll
    for (int i = 0; i < 8; i++) {
        float x[8];
        float s = 0.f, s2 = 0.f;
#pragma unroll
        for (int j = 0; j < 8; j++) {
            x[j] = fmaxf(c[i][j] + bj[j], 0.f);
            s += x[j];
            s2 += x[j] * x[j];
        }
#pragma unroll
        for (int off = 8; off >= 1; off >>= 1) {
            s  += __shfl_xor_sync(0xffffffffu, s,  off, 16);
            s2 += __shfl_xor_sync(0xffffffffu, s2, off, 16);
        }
        float mu = s * (1.f / 128.f);
        float var = s2 * (1.f / 128.f) - mu * mu;
        float inv = rsqrtf(fmaxf(var, 0.f) + 1e-5f);
        int m = m0 + ty * 8 + i;
#pragma unroll
        for (int jg = 0; jg < 2; jg++) {
            float4 o;
            o.x = (x[jg * 4 + 0] - mu) * inv * gj[jg * 4 + 0] + bb[jg * 4 + 0];
            o.y = (x[jg * 4 + 1] - mu) * inv * gj[jg * 4 + 1] + bb[jg * 4 + 1];
            o.z = (x[jg * 4 + 2] - mu) * inv * gj[jg * 4 + 2] + bb[jg * 4 + 2];
            o.w = (x[jg * 4 + 3] - mu) * inv * gj[jg * 4 + 3] + bb[jg * 4 + 3];
            *(float4*)&out[(size_t)m * DD + tx * 8 + jg * 4] = o;
        }
    }
}

// ---------------- launch ----------------
extern "C" void kernel_launch(void* const* d_in, const int* in_sizes, int n_in,
                              void* d_out, int out_size) {
    const float* h    = (const float*)d_in[0];
    const float* f    = (const float*)d_in[1];
    const float* dt   = (const float*)d_in[2];
    const int*   dst  = (const int*)d_in[3];
    const float* freq = (const float*)d_in[4];
    const float* tb   = (const float*)d_in[5];
    const float* Wq   = (const float*)d_in[6];
    const float* bq   = (const float*)d_in[7];
    const float* Wk   = (const float*)d_in[8];
    const float* bk   = (const float*)d_in[9];
    const float* Wv   = (const float*)d_in[10];
    const float* bv   = (const float*)d_in[11];
    const float* Wout = (const float*)d_in[12];
    const float* bout = (const float*)d_in[13];
    const float* gam  = (const float*)d_in[14];
    const float* bet  = (const float*)d_in[15];
    float* out = (float*)d_out;

    cudaFuncSetAttribute(k_kv, cudaFuncAttributeMaxDynamicSharedMemorySize, KV_SMEM);

    k_wconv<<<48, 1024>>>(Wk, Wv);
    k_bqeff<<<1, 128>>>(Wq, bq, tb);
    k_zero<<<ND / 256, 256>>>();
    k_count<<<NE / 256, 256>>>(dst);
    k_scan<<<1, 1024>>>();
    k_scatter<<<NE / 256, 256>>>(dst);
    k_gemmQ<<<ND / 128, 256>>>(h, Wq);
    k_kv<<<NE / 128, 512, KV_SMEM>>>(h, f, dt, freq, tb, bk, bv, dst);
    k_node<<<ND / 8, 256>>>();
    k_gemmOut<<<ND / 128, 256>>>(h, Wout, bout, gam, bet, out);
}